// round 2
// baseline (speedup 1.0000x reference)
#include <cuda_runtime.h>
#include <math.h>

// ---------------- problem constants ----------------
#define BB 2
#define SS 2048
#define DD 1024
#define NHH 16
#define DHH 64
#define NIAFH 4
#define QKVD 1024
#define MLPD 4096
#define ZD 32
#define HIAFD 128
#define RG 8
#define KVL (SS + RG)          // 2056
#define UPN (QKVD + 2*QKVD + 2*MLPD)   // 11264
#define UPK (DD + ZD)          // 1056
#define DWK (ZD + QKVD + MLPD) // 5152
#define NTOK (BB*SS)           // 4096

#define ZSCALE 0.04419417382415922f    // sqrt(1/(32*16))
#define SPSHIFT 0.5413248546129181f    // log(e-1)
#define NEGV -1000000000.0f

// output layout: h_out | z | mu | sigma
#define OFF_Z  (NTOK*DD)
#define OFF_MU (OFF_Z + NTOK*ZD)
#define OFF_SG (OFF_MU + NTOK*ZD)

// ---------------- scratch (static device memory; allocation-free rule) ----------------
__device__ float g_xz[(size_t)NTOK*UPK];             // [x | z]  (17 MB)
__device__ float g_u[(size_t)NTOK*UPN];              // up-proj output (184 MB)
__device__ float g_Q[(size_t)BB*NHH*SS*DHH];         // roped Q  (16 MB)
__device__ float g_K[(size_t)BB*NHH*KVL*DHH];        // registers + roped K (17 MB)
__device__ float g_V[(size_t)BB*NHH*KVL*DHH];        // registers + V (17 MB)
__device__ float g_scores[(size_t)BB*NHH*SS*KVL];    // attention matrix (539 MB)
__device__ float g_down[(size_t)NTOK*DWK];           // [z | attn | mlp] (84 MB)
__device__ int   g_mask_mode;                        // 0=u8, 1=i32, 2=f32

// ---------------- f32x2 packed-FMA helpers (Blackwell) ----------------
__device__ __forceinline__ unsigned long long pk2(float lo, float hi) {
    unsigned long long r;
    asm("mov.b64 %0, {%1, %2};" : "=l"(r) : "f"(lo), "f"(hi));
    return r;
}
__device__ __forceinline__ void upk2(unsigned long long v, float* lo, float* hi) {
    asm("mov.b64 {%0, %1}, %2;" : "=f"(*lo), "=f"(*hi) : "l"(v));
}
__device__ __forceinline__ void fma2(unsigned long long& d, unsigned long long a, unsigned long long b) {
    asm("fma.rn.f32x2 %0, %1, %2, %0;" : "+l"(d) : "l"(a), "l"(b));
}

// =======================================================================
// Kernel 0: classify the storage dtype of the bool `mask` input.
// Reads only the first 4096 bytes, which is in-bounds under every
// hypothesis (u8: 4096 B; i32: 16 KB; f32: 16 KB).
// =======================================================================
__global__ void detect_mask_kernel(const unsigned char* __restrict__ p)
{
    if (threadIdx.x != 0 || blockIdx.x != 0) return;
    const unsigned int* w = (const unsigned int*)p;
    bool allf = true, anyf = false, i32ok = true;
    for (int i = 0; i < 1024; i++) {
        unsigned int v = w[i];
        if (v == 0x3F800000u) anyf = true;
        else if (v != 0u) allf = false;
        if ((v & 0xFFFFFF00u) != 0u) i32ok = false;
    }
    g_mask_mode = (allf && anyf) ? 2 : (i32ok ? 1 : 0);
}

__device__ __forceinline__ float read_mask(const unsigned char* p, int m, int mode)
{
    if (mode == 1) return ((const int*)p)[m] != 0 ? 1.f : 0.f;
    if (mode == 2) return ((const float*)p)[m] != 0.f ? 1.f : 0.f;
    return p[m] != 0 ? 1.f : 0.f;
}

// =======================================================================
// Kernel 1: per-token LayerNorm + IAF encoder + z/mu/sigma (8 tokens/block)
// =======================================================================
__global__ void __launch_bounds__(128) token_kernel(
    const float* __restrict__ hs, const unsigned char* __restrict__ mask,
    const float* __restrict__ noise,
    const float* __restrict__ ln_w, const float* __restrict__ ln_b,
    const float* __restrict__ iaf_wx, const float* __restrict__ iaf_wn,
    const float* __restrict__ iaf_w2, float* __restrict__ out)
{
    __shared__ float xs[8][DD];
    __shared__ float ns[8][ZD];
    __shared__ float hdn[8][HIAFD];
    __shared__ float zps[8][2*ZD];
    __shared__ float fmv[8];
    __shared__ float redS[4], redQ[4], stat[2];

    const int tid = threadIdx.x, lane = tid & 31, wid = tid >> 5;
    const int m0 = blockIdx.x * 8;
    const int mmode = g_mask_mode;

    for (int idx = tid; idx < 8*ZD; idx += 128) {
        int t = idx >> 5, i = idx & 31;
        float fm = read_mask(mask, m0 + t, mmode);
        ns[t][i] = noise[(size_t)(m0 + t)*ZD + i] * fm;
        if (i == 0) fmv[t] = fm;
    }

    for (int t = 0; t < 8; t++) {
        const int m = m0 + t;
        const float* hp = hs + (size_t)m*DD;
        float s = 0.f, q = 0.f;
        #pragma unroll
        for (int k = 0; k < 8; k++) {
            float v = hp[tid + k*128];
            xs[t][tid + k*128] = v;
            s += v; q += v*v;
        }
        #pragma unroll
        for (int o = 16; o; o >>= 1) {
            s += __shfl_down_sync(0xffffffffu, s, o);
            q += __shfl_down_sync(0xffffffffu, q, o);
        }
        if (lane == 0) { redS[wid] = s; redQ[wid] = q; }
        __syncthreads();
        if (tid == 0) {
            float S1 = redS[0]+redS[1]+redS[2]+redS[3];
            float Q1 = redQ[0]+redQ[1]+redQ[2]+redQ[3];
            float mean = S1 / (float)DD;
            float var  = Q1 / (float)DD - mean*mean;
            stat[0] = mean;
            stat[1] = rsqrtf(var + 1e-5f);
        }
        __syncthreads();
        float mean = stat[0], rstd = stat[1];
        float* xzr = g_xz + (size_t)m*UPK;
        #pragma unroll
        for (int k = 0; k < 8; k++) {
            int d = tid + k*128;
            float x = (xs[t][d] - mean)*rstd*ln_w[d] + ln_b[d];
            xs[t][d] = x;
            xzr[d] = x;
        }
        __syncthreads();
    }

    // hdn = silu(x @ iaf_wx^T + noise @ (iaf_wn*M1)^T); thread j handles row j
    {
        int j = tid;
        float acc[8];
        #pragma unroll
        for (int t = 0; t < 8; t++) acc[t] = 0.f;
        const float* wx = iaf_wx + (size_t)j*DD;
        for (int d = 0; d < DD; d++) {
            float w = wx[d];
            #pragma unroll
            for (int t = 0; t < 8; t++) acc[t] += xs[t][d]*w;
        }
        int dm = j % 31;                  // M1[j][i] = (i <= j%31)
        const float* wn = iaf_wn + (size_t)j*ZD;
        for (int i = 0; i <= dm; i++) {
            float w = wn[i];
            #pragma unroll
            for (int t = 0; t < 8; t++) acc[t] += ns[t][i]*w;
        }
        #pragma unroll
        for (int t = 0; t < 8; t++) {
            float v = acc[t];
            hdn[t][j] = v / (1.f + __expf(-v));
        }
    }
    __syncthreads();

    // zp = fm * ZSCALE * (hdn @ (iaf_w2*M2)^T); thread o<64 handles out-row o
    if (tid < 64) {
        int o = tid, lim = o & 31;        // M2[o][j] = (j%31 < o%32)
        float acc[8];
        #pragma unroll
        for (int t = 0; t < 8; t++) acc[t] = 0.f;
        const float* w2 = iaf_w2 + (size_t)o*HIAFD;
        for (int j = 0; j < HIAFD; j++) {
            if ((j % 31) < lim) {
                float w = w2[j];
                #pragma unroll
                for (int t = 0; t < 8; t++) acc[t] += hdn[t][j]*w;
            }
        }
        #pragma unroll
        for (int t = 0; t < 8; t++) zps[t][o] = fmv[t]*ZSCALE*acc[t];
    }
    __syncthreads();

    for (int idx = tid; idx < 8*ZD; idx += 128) {
        int t = idx >> 5, i = idx & 31;
        int m = m0 + t;
        float mu = zps[t][i];
        float ls = zps[t][ZD + i] + SPSHIFT;
        float sg = (ls > 20.f) ? ls : log1pf(expf(ls));
        float z  = mu + sg*ns[t][i];
        g_xz[(size_t)m*UPK + DD + i] = z;
        g_down[(size_t)m*DWK + i]    = z;
        out[OFF_Z  + (size_t)m*ZD + i] = z;
        out[OFF_MU + (size_t)m*ZD + i] = mu;
        out[OFF_SG + (size_t)m*ZD + i] = sg;
    }
}

// =======================================================================
// Kernel 2: generic NT SGEMM (C[m,n] = A[m,:].B[n,:]) 128x128x8, f32x2 FMA
//   EPI: C = addsrc + alpha * acc  (down-proj residual epilogue)
//   Requires M%128==0, N%128==0, K%8==0, rows 16B aligned.
// =======================================================================
template<bool EPI>
__global__ void __launch_bounds__(256) sgemm_nt(
    const float* __restrict__ A, const float* __restrict__ Bw, float* __restrict__ C,
    int M, int N, int K, const float* __restrict__ addsrc, const float* __restrict__ alphap)
{
    __shared__ float As[8][128];
    __shared__ float Bs[8][128];
    const int tid = threadIdx.x;
    const int bm = blockIdx.y*128, bn = blockIdx.x*128;
    const int lr = tid >> 1, lc = (tid & 1)*4;
    const float* Ap = A + (size_t)(bm + lr)*K + lc;
    const float* Bp = Bw + (size_t)(bn + lr)*K + lc;
    const int tx = tid & 15, ty = tid >> 4;

    unsigned long long acc[8][4];
    #pragma unroll
    for (int r = 0; r < 8; r++)
        #pragma unroll
        for (int c = 0; c < 4; c++) acc[r][c] = 0ull;

    for (int k0 = 0; k0 < K; k0 += 8) {
        float4 a4 = *(const float4*)(Ap + k0);
        float4 b4 = *(const float4*)(Bp + k0);
        As[lc+0][lr] = a4.x; As[lc+1][lr] = a4.y; As[lc+2][lr] = a4.z; As[lc+3][lr] = a4.w;
        Bs[lc+0][lr] = b4.x; Bs[lc+1][lr] = b4.y; Bs[lc+2][lr] = b4.z; Bs[lc+3][lr] = b4.w;
        __syncthreads();
        #pragma unroll
        for (int kk = 0; kk < 8; kk++) {
            float4 a0 = *(const float4*)&As[kk][ty*4];
            float4 a1 = *(const float4*)&As[kk][64 + ty*4];
            float4 b0 = *(const float4*)&Bs[kk][tx*4];
            float4 b1 = *(const float4*)&Bs[kk][64 + tx*4];
            unsigned long long bb0 = pk2(b0.x, b0.y), bb1 = pk2(b0.z, b0.w);
            unsigned long long bb2 = pk2(b1.x, b1.y), bb3 = pk2(b1.z, b1.w);
            float ar[8] = {a0.x, a0.y, a0.z, a0.w, a1.x, a1.y, a1.z, a1.w};
            #pragma unroll
            for (int r = 0; r < 8; r++) {
                unsigned long long a2 = pk2(ar[r], ar[r]);
                fma2(acc[r][0], a2, bb0);
                fma2(acc[r][1], a2, bb1);
                fma2(acc[r][2], a2, bb2);
                fma2(acc[r][3], a2, bb3);
            }
        }
        __syncthreads();
    }

    float alpha = EPI ? *alphap : 0.f;
    #pragma unroll
    for (int r = 0; r < 8; r++) {
        int gr = bm + ((r < 4) ? (ty*4 + r) : (64 + ty*4 + r - 4));
        #pragma unroll
        for (int c = 0; c < 4; c++) {
            int gc = bn + ((c < 2) ? (tx*4 + c*2) : (64 + tx*4 + (c - 2)*2));
            float v0, v1; upk2(acc[r][c], &v0, &v1);
            size_t o0 = (size_t)gr*N + gc;
            if (EPI) {
                C[o0]   = addsrc[o0]   + alpha*v0;
                C[o0+1] = addsrc[o0+1] + alpha*v1;
            } else {
                C[o0] = v0; C[o0+1] = v1;
            }
        }
    }
}

// =======================================================================
// Kernel 3: QKV prep — IAF-up add on k/v (heads<4), RoPE q/k, head-major store
// =======================================================================
__global__ void __launch_bounds__(256) prep_qkv(
    const float* __restrict__ next_noise, const float* __restrict__ iaf_up_w)
{
    __shared__ float nn[ZD];
    __shared__ float kadd[256], vadd[256];
    const int m = blockIdx.x;
    const int b = m >> 11, spos = m & 2047;
    const int tid = threadIdx.x;

    if (tid < ZD) nn[tid] = next_noise[(size_t)m*ZD + tid];
    __syncthreads();
    {
        float ka = 0.f, va = 0.f;
        const float* wk = iaf_up_w + (size_t)tid*ZD;
        const float* wv = iaf_up_w + (size_t)(QKVD + tid)*ZD;
        #pragma unroll 8
        for (int i = 0; i < ZD; i++) { ka += nn[i]*wk[i]; va += nn[i]*wv[i]; }
        kadd[tid] = ka; vadd[tid] = va;
    }
    __syncthreads();

    const float* um = g_u + (size_t)m*UPN;
    for (int p = tid; p < 512; p += 256) {
        int hh = p >> 5, dd = p & 31;
        // inv = 1/10000^(2dd/64), matching reference's two-rounding form
        float pw  = (float)exp((double)(2*dd)*(1.0/64.0)*log(10000.0));
        float inv = 1.0f / pw;
        float ang = (float)spos * inv;
        float c, sn; sincosf(ang, &sn, &c);
        int i1 = hh*DHH + dd, i2 = i1 + 32;
        // q
        float q1 = um[i1], q2 = um[i2];
        size_t qo = (((size_t)(b*NHH + hh))*SS + spos)*DHH;
        g_Q[qo + dd]      = q1*c - q2*sn;
        g_Q[qo + 32 + dd] = q2*c + q1*sn;
        // k (+ masked IAF up contribution, rows [0,256))
        float k1 = um[QKVD + i1] + (i1 < 256 ? kadd[i1] : 0.f);
        float k2 = um[QKVD + i2] + (i2 < 256 ? kadd[i2] : 0.f);
        size_t ko = (((size_t)(b*NHH + hh))*KVL + RG + spos)*DHH;
        g_K[ko + dd]      = k1*c - k2*sn;
        g_K[ko + 32 + dd] = k2*c + k1*sn;
    }
    for (int p = tid; p < QKVD; p += 256) {
        int hh = p >> 6;
        float vv = um[2*QKVD + p] + (p < 256 ? vadd[p] : 0.f);
        g_V[(((size_t)(b*NHH + hh))*KVL + RG + spos)*DHH + (p & 63)] = vv;
    }
}

// register tokens K/V fill
__global__ void regfill_kernel(const float* __restrict__ reg_k, const float* __restrict__ reg_v)
{
    int bh = blockIdx.x, hh = bh & 15;
    int j = threadIdx.x >> 6, d = threadIdx.x & 63;
    g_K[((size_t)bh*KVL + j)*DHH + d] = reg_k[((size_t)j*NHH + hh)*DHH + d];
    g_V[((size_t)bh*KVL + j)*DHH + d] = reg_v[((size_t)j*NHH + hh)*DHH + d];
}

// =======================================================================
// Kernel 4: scores = Q K^T / 8 + mask  (NT GEMM, K=64, fused mask epilogue)
// =======================================================================
__global__ void __launch_bounds__(256) scores_kernel(const float* __restrict__ attn_mask)
{
    __shared__ float As[8][128];
    __shared__ float Bs[8][128];
    const int bh = blockIdx.z, b = bh >> 4, hh = bh & 15;
    const int tid = threadIdx.x;
    const int bm = blockIdx.y*128, bn = blockIdx.x*128;
    const int lr = tid >> 1, lc = (tid & 1)*4;
    const float* Ap = g_Q + (size_t)bh*SS*DHH  + (size_t)(bm + lr)*DHH + lc;
    const bool bok = (bn + lr) < KVL;
    const float* Bp = g_K + (size_t)bh*KVL*DHH + (size_t)(bn + lr)*DHH + lc;
    const int tx = tid & 15, ty = tid >> 4;

    unsigned long long acc[8][4];
    #pragma unroll
    for (int r = 0; r < 8; r++)
        #pragma unroll
        for (int c = 0; c < 4; c++) acc[r][c] = 0ull;

    for (int k0 = 0; k0 < DHH; k0 += 8) {
        float4 a4 = *(const float4*)(Ap + k0);
        float4 b4 = bok ? *(const float4*)(Bp + k0) : make_float4(0.f, 0.f, 0.f, 0.f);
        As[lc+0][lr] = a4.x; As[lc+1][lr] = a4.y; As[lc+2][lr] = a4.z; As[lc+3][lr] = a4.w;
        Bs[lc+0][lr] = b4.x; Bs[lc+1][lr] = b4.y; Bs[lc+2][lr] = b4.z; Bs[lc+3][lr] = b4.w;
        __syncthreads();
        #pragma unroll
        for (int kk = 0; kk < 8; kk++) {
            float4 a0 = *(const float4*)&As[kk][ty*4];
            float4 a1 = *(const float4*)&As[kk][64 + ty*4];
            float4 b0 = *(const float4*)&Bs[kk][tx*4];
            float4 b1 = *(const float4*)&Bs[kk][64 + tx*4];
            unsigned long long bb0 = pk2(b0.x, b0.y), bb1 = pk2(b0.z, b0.w);
            unsigned long long bb2 = pk2(b1.x, b1.y), bb3 = pk2(b1.z, b1.w);
            float ar[8] = {a0.x, a0.y, a0.z, a0.w, a1.x, a1.y, a1.z, a1.w};
            #pragma unroll
            for (int r = 0; r < 8; r++) {
                unsigned long long a2 = pk2(ar[r], ar[r]);
                fma2(acc[r][0], a2, bb0);
                fma2(acc[r][1], a2, bb1);
                fma2(acc[r][2], a2, bb2);
                fma2(acc[r][3], a2, bb3);
            }
        }
        __syncthreads();
    }

    #pragma unroll
    for (int r = 0; r < 8; r++) {
        int gi = bm + ((r < 4) ? (ty*4 + r) : (64 + ty*4 + r - 4));
        size_t srow  = ((size_t)bh*SS + gi)*KVL;
        size_t amrow = ((size_t)b*SS + gi)*SS;
        #pragma unroll
        for (int c = 0; c < 4; c++) {
            int gj0 = bn + ((c < 2) ? (tx*4 + c*2) : (64 + tx*4 + (c - 2)*2));
            float v0, v1; upk2(acc[r][c], &v0, &v1);
            #pragma unroll
            for (int e = 0; e < 2; e++) {
                int gj = gj0 + e;
                float v = (e == 0) ? v0 : v1;
                if (gj < KVL) {
                    float msk = 0.f;
                    if (gj >= RG) {
                        int js = gj - RG;
                        msk = attn_mask[amrow + js];
                        if (hh < NIAFH && js >= gi) msk += NEGV;
                    }
                    g_scores[srow + gj] = 0.125f*v + msk;
                }
            }
        }
    }
}

// =======================================================================
// Kernel 5: row softmax over 2056 keys (in place)
// =======================================================================
__global__ void __launch_bounds__(256) softmax_kernel()
{
    float* p = g_scores + (size_t)blockIdx.x*KVL;
    __shared__ float red[8];
    __shared__ float bval;
    const int tid = threadIdx.x, lane = tid & 31, wid = tid >> 5;

    float mx = -3.4e38f;
    for (int j = tid; j < KVL; j += 256) mx = fmaxf(mx, p[j]);
    #pragma unroll
    for (int o = 16; o; o >>= 1) mx = fmaxf(mx, __shfl_xor_sync(0xffffffffu, mx, o));
    if (lane == 0) red[wid] = mx;
    __syncthreads();
    if (tid == 0) {
        float m2 = red[0];
        for (int i = 1; i < 8; i++) m2 = fmaxf(m2, red[i]);
        bval = m2;
    }
    __syncthreads();
    mx = bval;

    float sum = 0.f;
    for (int j = tid; j < KVL; j += 256) {
        float e = __expf(p[j] - mx);
        p[j] = e;
        sum += e;
    }
    #pragma unroll
    for (int o = 16; o; o >>= 1) sum += __shfl_xor_sync(0xffffffffu, sum, o);
    if (lane == 0) red[wid] = sum;
    __syncthreads();
    if (tid == 0) {
        float s2 = 0.f;
        for (int i = 0; i < 8; i++) s2 += red[i];
        bval = 1.f / s2;
    }
    __syncthreads();
    float inv = bval;
    for (int j = tid; j < KVL; j += 256) p[j] *= inv;
}

// =======================================================================
// Kernel 6: attn_out = P @ V (NN GEMM 128x64, K=2056), writes into g_down
// =======================================================================
__global__ void __launch_bounds__(256) pv_kernel()
{
    __shared__ float As[8][128];
    __shared__ float Bs[8][64];
    const int bh = blockIdx.z, b = bh >> 4, hh = bh & 15;
    const int tid = threadIdx.x;
    const int bm = blockIdx.y*128;
    const float* Ap = g_scores + (size_t)bh*SS*KVL + (size_t)(bm + (tid >> 1))*KVL + (tid & 1)*4;
    const float* Vb = g_V + (size_t)bh*KVL*DHH;
    const int lr = tid >> 1, lc = (tid & 1)*4;
    const int bj = tid >> 5, bd = (tid & 31)*2;
    const int tx = tid & 15, ty = tid >> 4;

    unsigned long long acc[8][2];
    #pragma unroll
    for (int r = 0; r < 8; r++) { acc[r][0] = 0ull; acc[r][1] = 0ull; }

    for (int k0 = 0; k0 < KVL; k0 += 8) {            // 2056 % 8 == 0
        float4 a4 = *(const float4*)(Ap + k0);
        float2 v2 = *(const float2*)(Vb + (size_t)(k0 + bj)*DHH + bd);
        As[lc+0][lr] = a4.x; As[lc+1][lr] = a4.y; As[lc+2][lr] = a4.z; As[lc+3][lr] = a4.w;
        Bs[bj][bd] = v2.x; Bs[bj][bd+1] = v2.y;
        __syncthreads();
        #pragma unroll
        for (int kk = 0; kk < 8; kk++) {
            float4 a0 = *(const float4*)&As[kk][ty*4];
            float4 a1 = *(const float4*)&As[kk][64 + ty*4];
            float4 b0 = *(const float4*)&Bs[kk][tx*4];
            unsigned long long bb0 = pk2(b0.x, b0.y), bb1 = pk2(b0.z, b0.w);
            float ar[8] = {a0.x, a0.y, a0.z, a0.w, a1.x, a1.y, a1.z, a1.w};
            #pragma unroll
            for (int r = 0; r < 8; r++) {
                unsigned long long a2 = pk2(ar[r], ar[r]);
                fma2(acc[r][0], a2, bb0);
                fma2(acc[r][1], a2, bb1);
            }
        }
        __syncthreads();
    }

    #pragma unroll
    for (int r = 0; r < 8; r++) {
        int gi = bm + ((r < 4) ? (ty*4 + r) : (64 + ty*4 + r - 4));
        int m = b*SS + gi;
        size_t base = (size_t)m*DWK + ZD + hh*DHH + tx*4;
        float v0, v1;
        upk2(acc[r][0], &v0, &v1);
        g_down[base + 0] = v0; g_down[base + 1] = v1;
        upk2(acc[r][1], &v0, &v1);
        g_down[base + 2] = v0; g_down[base + 3] = v1;
    }
}

// =======================================================================
// Kernel 7: mlp = silu(gate)*val into g_down
// =======================================================================
__global__ void __launch_bounds__(256) mlp_kernel()
{
    size_t idx = (size_t)blockIdx.x*256 + threadIdx.x;
    int m = (int)(idx >> 12);
    int j = (int)(idx & 4095);
    float g = g_u[(size_t)m*UPN + 3*QKVD + j];
    float v = g_u[(size_t)m*UPN + 3*QKVD + MLPD + j];
    g_down[(size_t)m*DWK + ZD + QKVD + j] = g / (1.f + __expf(-g)) * v;
}

// =======================================================================
// launch
// =======================================================================
extern "C" void kernel_launch(void* const* d_in, const int* in_sizes, int n_in,
                              void* d_out, int out_size)
{
    const float* hs          = (const float*)d_in[0];
    const unsigned char* msk = (const unsigned char*)d_in[1];
    const float* noise       = (const float*)d_in[2];
    const float* next_noise  = (const float*)d_in[3];
    const float* attn_mask   = (const float*)d_in[4];
    const float* ln_w        = (const float*)d_in[5];
    const float* ln_b        = (const float*)d_in[6];
    const float* alpha       = (const float*)d_in[7];
    const float* iaf_wx      = (const float*)d_in[8];
    const float* iaf_wn      = (const float*)d_in[9];
    const float* iaf_w2      = (const float*)d_in[10];
    const float* up_w        = (const float*)d_in[11];
    const float* iaf_up_w    = (const float*)d_in[12];
    const float* down_w      = (const float*)d_in[13];
    const float* reg_k       = (const float*)d_in[14];
    const float* reg_v       = (const float*)d_in[15];
    float* out = (float*)d_out;

    float *p_xz, *p_u, *p_down;
    cudaGetSymbolAddress((void**)&p_xz, g_xz);
    cudaGetSymbolAddress((void**)&p_u, g_u);
    cudaGetSymbolAddress((void**)&p_down, g_down);

    detect_mask_kernel<<<1, 32>>>(msk);

    token_kernel<<<NTOK/8, 128>>>(hs, msk, noise, ln_w, ln_b, iaf_wx, iaf_wn, iaf_w2, out);

    sgemm_nt<false><<<dim3(UPN/128, NTOK/128), 256>>>(p_xz, up_w, p_u,
                                                      NTOK, UPN, UPK, nullptr, nullptr);

    prep_qkv<<<NTOK, 256>>>(next_noise, iaf_up_w);
    regfill_kernel<<<BB*NHH, 512>>>(reg_k, reg_v);

    scores_kernel<<<dim3((KVL + 127)/128, SS/128, BB*NHH), 256>>>(attn_mask);
    softmax_kernel<<<BB*NHH*SS, 256>>>();
    pv_kernel<<<dim3(1, SS/128, BB*NHH), 256>>>();

    mlp_kernel<<<(NTOK*MLPD)/256, 256>>>();

    sgemm_nt<true><<<dim3(DD/128, NTOK/128), 256>>>(p_down, down_w, out,
                                                    NTOK, DD, DWK, hs, alpha);
}

// round 7
// speedup vs baseline: 1.7483x; 1.7483x over previous
#include <cuda_runtime.h>
#include <math.h>

// ---------------- problem constants ----------------
#define BB 2
#define SS 2048
#define DD 1024
#define NHH 16
#define DHH 64
#define NIAFH 4
#define QKVD 1024
#define MLPD 4096
#define ZD 32
#define HIAFD 128
#define RG 8
#define KVL (SS + RG)          // 2056
#define KVS 2080               // padded key length (multiple of 32)
#define UPN (QKVD + 2*QKVD + 2*MLPD)   // 11264
#define UPK (DD + ZD)          // 1056
#define DWK (ZD + QKVD + MLPD) // 5152
#define NTOK (BB*SS)           // 4096

#define ZSCALE 0.04419417382415922f    // sqrt(1/(32*16))
#define SPSHIFT 0.5413248546129181f    // log(e-1)
#define NEGV -1000000000.0f

// output layout: h_out | z | mu | sigma
#define OFF_Z  (NTOK*DD)
#define OFF_MU (OFF_Z + NTOK*ZD)
#define OFF_SG (OFF_MU + NTOK*ZD)

// ---------------- scratch (static device memory; allocation-free rule) ----------------
__device__ float g_xz[(size_t)NTOK*UPK];             // [x | z]
__device__ float g_u[(size_t)NTOK*UPN];              // up-proj output
__device__ float g_Q[(size_t)BB*NHH*SS*DHH];         // roped Q
__device__ float g_K[(size_t)BB*NHH*KVL*DHH];        // registers + roped K
__device__ float g_V[(size_t)BB*NHH*KVS*DHH];        // registers + V (padded rows zero)
__device__ float g_scores[(size_t)BB*NHH*SS*KVS];    // attention matrix (padded cols zero)
__device__ float g_down[(size_t)NTOK*DWK];           // [z | attn | mlp]
__device__ int   g_mask_mode;                        // 0=u8, 1=i32, 2=f32

struct RopeTab { float inv[32]; };

// ---------------- tf32 mma helpers ----------------
__device__ __forceinline__ unsigned cvt_tf32(float x) {
    unsigned r;
    asm("cvt.rna.tf32.f32 %0, %1;" : "=r"(r) : "f"(x));
    return r;
}
__device__ __forceinline__ float cvtf(float x) { return __uint_as_float(cvt_tf32(x)); }

__device__ __forceinline__ void mma8(float* d, const unsigned* a, const unsigned* b) {
    asm volatile(
        "mma.sync.aligned.m16n8k8.row.col.f32.tf32.tf32.f32 "
        "{%0,%1,%2,%3}, {%4,%5,%6,%7}, {%8,%9}, {%0,%1,%2,%3};"
        : "+f"(d[0]), "+f"(d[1]), "+f"(d[2]), "+f"(d[3])
        : "r"(a[0]), "r"(a[1]), "r"(a[2]), "r"(a[3]), "r"(b[0]), "r"(b[1]));
}
__device__ __forceinline__ unsigned ldsu(const float* p) { return __float_as_uint(*p); }

// =======================================================================
// Kernel 0: classify the storage dtype of the bool `mask` input.
// =======================================================================
__global__ void detect_mask_kernel(const unsigned char* __restrict__ p)
{
    if (threadIdx.x != 0 || blockIdx.x != 0) return;
    const unsigned int* w = (const unsigned int*)p;
    bool allf = true, anyf = false, i32ok = true;
    for (int i = 0; i < 1024; i++) {
        unsigned int v = w[i];
        if (v == 0x3F800000u) anyf = true;
        else if (v != 0u) allf = false;
        if ((v & 0xFFFFFF00u) != 0u) i32ok = false;
    }
    g_mask_mode = (allf && anyf) ? 2 : (i32ok ? 1 : 0);
}

__device__ __forceinline__ float read_mask(const unsigned char* p, int m, int mode)
{
    if (mode == 1) return ((const int*)p)[m] != 0 ? 1.f : 0.f;
    if (mode == 2) return ((const float*)p)[m] != 0.f ? 1.f : 0.f;
    return p[m] != 0 ? 1.f : 0.f;
}

// =======================================================================
// Kernel 1: per-token LayerNorm + IAF encoder + z/mu/sigma (8 tokens/block)
// =======================================================================
__global__ void __launch_bounds__(128) token_kernel(
    const float* __restrict__ hs, const unsigned char* __restrict__ mask,
    const float* __restrict__ noise,
    const float* __restrict__ ln_w, const float* __restrict__ ln_b,
    const float* __restrict__ iaf_wx, const float* __restrict__ iaf_wn,
    const float* __restrict__ iaf_w2, float* __restrict__ out)
{
    __shared__ float xs[8][DD];
    __shared__ float ns[8][ZD];
    __shared__ float hdn[8][HIAFD];
    __shared__ float zps[8][2*ZD];
    __shared__ float fmv[8];
    __shared__ float redS[4], redQ[4], stat[2];

    const int tid = threadIdx.x, lane = tid & 31, wid = tid >> 5;
    const int m0 = blockIdx.x * 8;
    const int mmode = g_mask_mode;

    for (int idx = tid; idx < 8*ZD; idx += 128) {
        int t = idx >> 5, i = idx & 31;
        float fm = read_mask(mask, m0 + t, mmode);
        ns[t][i] = noise[(size_t)(m0 + t)*ZD + i] * fm;
        if (i == 0) fmv[t] = fm;
    }

    for (int t = 0; t < 8; t++) {
        const int m = m0 + t;
        const float* hp = hs + (size_t)m*DD;
        float s = 0.f, q = 0.f;
        #pragma unroll
        for (int k = 0; k < 8; k++) {
            float v = hp[tid + k*128];
            xs[t][tid + k*128] = v;
            s += v; q += v*v;
        }
        #pragma unroll
        for (int o = 16; o; o >>= 1) {
            s += __shfl_down_sync(0xffffffffu, s, o);
            q += __shfl_down_sync(0xffffffffu, q, o);
        }
        if (lane == 0) { redS[wid] = s; redQ[wid] = q; }
        __syncthreads();
        if (tid == 0) {
            float S1 = redS[0]+redS[1]+redS[2]+redS[3];
            float Q1 = redQ[0]+redQ[1]+redQ[2]+redQ[3];
            float mean = S1 / (float)DD;
            float var  = Q1 / (float)DD - mean*mean;
            stat[0] = mean;
            stat[1] = rsqrtf(var + 1e-5f);
        }
        __syncthreads();
        float mean = stat[0], rstd = stat[1];
        float* xzr = g_xz + (size_t)m*UPK;
        #pragma unroll
        for (int k = 0; k < 8; k++) {
            int d = tid + k*128;
            float x = (xs[t][d] - mean)*rstd*ln_w[d] + ln_b[d];
            xs[t][d] = x;
            xzr[d] = x;
        }
        __syncthreads();
    }

    // hdn = silu(x @ iaf_wx^T + noise @ (iaf_wn*M1)^T); thread j handles row j
    {
        int j = tid;
        float acc[8];
        #pragma unroll
        for (int t = 0; t < 8; t++) acc[t] = 0.f;
        const float* wx = iaf_wx + (size_t)j*DD;
        for (int d = 0; d < DD; d++) {
            float w = wx[d];
            #pragma unroll
            for (int t = 0; t < 8; t++) acc[t] += xs[t][d]*w;
        }
        int dm = j % 31;                  // M1[j][i] = (i <= j%31)
        const float* wn = iaf_wn + (size_t)j*ZD;
        for (int i = 0; i <= dm; i++) {
            float w = wn[i];
            #pragma unroll
            for (int t = 0; t < 8; t++) acc[t] += ns[t][i]*w;
        }
        #pragma unroll
        for (int t = 0; t < 8; t++) {
            float v = acc[t];
            hdn[t][j] = v / (1.f + __expf(-v));
        }
    }
    __syncthreads();

    // zp = fm * ZSCALE * (hdn @ (iaf_w2*M2)^T)
    if (tid < 64) {
        int o = tid, lim = o & 31;        // M2[o][j] = (j%31 < o%32)
        float acc[8];
        #pragma unroll
        for (int t = 0; t < 8; t++) acc[t] = 0.f;
        const float* w2 = iaf_w2 + (size_t)o*HIAFD;
        for (int j = 0; j < HIAFD; j++) {
            if ((j % 31) < lim) {
                float w = w2[j];
                #pragma unroll
                for (int t = 0; t < 8; t++) acc[t] += hdn[t][j]*w;
            }
        }
        #pragma unroll
        for (int t = 0; t < 8; t++) zps[t][o] = fmv[t]*ZSCALE*acc[t];
    }
    __syncthreads();

    for (int idx = tid; idx < 8*ZD; idx += 128) {
        int t = idx >> 5, i = idx & 31;
        int m = m0 + t;
        float mu = zps[t][i];
        float ls = zps[t][ZD + i] + SPSHIFT;
        float sg = (ls > 20.f) ? ls : log1pf(expf(ls));
        float z  = mu + sg*ns[t][i];
        g_xz[(size_t)m*UPK + DD + i] = z;
        g_down[(size_t)m*DWK + i]    = z;
        out[OFF_Z  + (size_t)m*ZD + i] = z;
        out[OFF_MU + (size_t)m*ZD + i] = mu;
        out[OFF_SG + (size_t)m*ZD + i] = sg;
    }
}

// =======================================================================
// Kernel 2: TF32 tensor-core NT GEMM, 128x256 block, 8 warps (64x64 each)
//   C[m,n] = sum_k A[m,k]*B[n,k];  EPI=1: C = addsrc + alpha*acc
//   Requires M%128==0, N%256==0, K%32==0.
//   Dynamic smem: (128*36 + 256*36)*4 = 55296 B
// =======================================================================
template<int EPI>
__global__ void __launch_bounds__(256) tf32_gemm_nt(
    const float* __restrict__ A, const float* __restrict__ B, float* __restrict__ C,
    int M, int N, int K, const float* __restrict__ addsrc, const float* __restrict__ alphap)
{
    extern __shared__ float sm[];
    float* As = sm;               // [128][36]
    float* Bs = sm + 128*36;      // [256][36]
    const int tid = threadIdx.x;
    const int lane = tid & 31, wid = tid >> 5;
    const int g = lane >> 2, t = lane & 3;
    const int wm = (wid >> 2) * 64, wn = (wid & 3) * 64;
    const int bm = blockIdx.y * 128, bn = blockIdx.x * 256;

    float acc[4][8][4];
    #pragma unroll
    for (int mi = 0; mi < 4; mi++)
        #pragma unroll
        for (int ni = 0; ni < 8; ni++)
            #pragma unroll
            for (int e = 0; e < 4; e++) acc[mi][ni][e] = 0.f;

    for (int k0 = 0; k0 < K; k0 += 32) {
        float4 av[4], bv[8];
        #pragma unroll
        for (int j = 0; j < 4; j++) {
            int idx = tid + j*256, r = idx >> 3, c4 = idx & 7;
            av[j] = *(const float4*)(A + (size_t)(bm + r)*K + k0 + c4*4);
        }
        #pragma unroll
        for (int j = 0; j < 8; j++) {
            int idx = tid + j*256, r = idx >> 3, c4 = idx & 7;
            bv[j] = *(const float4*)(B + (size_t)(bn + r)*K + k0 + c4*4);
        }
        __syncthreads();
        #pragma unroll
        for (int j = 0; j < 4; j++) {
            int idx = tid + j*256, r = idx >> 3, c4 = idx & 7;
            float* p = As + r*36 + c4*4;
            p[0] = cvtf(av[j].x); p[1] = cvtf(av[j].y);
            p[2] = cvtf(av[j].z); p[3] = cvtf(av[j].w);
        }
        #pragma unroll
        for (int j = 0; j < 8; j++) {
            int idx = tid + j*256, r = idx >> 3, c4 = idx & 7;
            float* p = Bs + r*36 + c4*4;
            p[0] = cvtf(bv[j].x); p[1] = cvtf(bv[j].y);
            p[2] = cvtf(bv[j].z); p[3] = cvtf(bv[j].w);
        }
        __syncthreads();
        #pragma unroll
        for (int ks = 0; ks < 32; ks += 8) {
            unsigned a[4][4], b[8][2];
            #pragma unroll
            for (int mi = 0; mi < 4; mi++) {
                const float* p0 = As + (wm + mi*16 + g)*36 + ks;
                const float* p1 = p0 + 8*36;
                a[mi][0] = ldsu(p0 + t);
                a[mi][1] = ldsu(p1 + t);
                a[mi][2] = ldsu(p0 + t + 4);
                a[mi][3] = ldsu(p1 + t + 4);
            }
            #pragma unroll
            for (int ni = 0; ni < 8; ni++) {
                const float* pn = Bs + (wn + ni*8 + g)*36 + ks;
                b[ni][0] = ldsu(pn + t);
                b[ni][1] = ldsu(pn + t + 4);
            }
            #pragma unroll
            for (int mi = 0; mi < 4; mi++)
                #pragma unroll
                for (int ni = 0; ni < 8; ni++)
                    mma8(acc[mi][ni], a[mi], b[ni]);
        }
        __syncthreads();
    }

    float alpha = (EPI == 1) ? *alphap : 0.f;
    #pragma unroll
    for (int mi = 0; mi < 4; mi++) {
        int r0 = bm + wm + mi*16 + g;
        #pragma unroll
        for (int ni = 0; ni < 8; ni++) {
            int c0 = bn + wn + ni*8 + 2*t;
            #pragma unroll
            for (int h = 0; h < 2; h++) {
                int row = r0 + 8*h;
                size_t o = (size_t)row*N + c0;
                float v0 = acc[mi][ni][2*h], v1 = acc[mi][ni][2*h + 1];
                if (EPI == 1) {
                    v0 = addsrc[o]   + alpha*v0;
                    v1 = addsrc[o+1] + alpha*v1;
                }
                float2 v = make_float2(v0, v1);
                *(float2*)(C + o) = v;
            }
        }
    }
}

// =======================================================================
// Kernel 3: QKV prep — IAF-up add on k/v, RoPE q/k, head-major store
// =======================================================================
__global__ void __launch_bounds__(256) prep_qkv(
    const float* __restrict__ next_noise, const float* __restrict__ iaf_up_w, RopeTab tab)
{
    __shared__ float nn[ZD];
    __shared__ float kadd[256], vadd[256];
    const int m = blockIdx.x;
    const int b = m >> 11, spos = m & 2047;
    const int tid = threadIdx.x;

    if (tid < ZD) nn[tid] = next_noise[(size_t)m*ZD + tid];
    __syncthreads();
    {
        float ka = 0.f, va = 0.f;
        const float* wk = iaf_up_w + (size_t)tid*ZD;
        const float* wv = iaf_up_w + (size_t)(QKVD + tid)*ZD;
        #pragma unroll 8
        for (int i = 0; i < ZD; i++) { ka += nn[i]*wk[i]; va += nn[i]*wv[i]; }
        kadd[tid] = ka; vadd[tid] = va;
    }
    __syncthreads();

    const float* um = g_u + (size_t)m*UPN;
    for (int p = tid; p < 512; p += 256) {
        int hh = p >> 5, dd = p & 31;
        float ang = (float)spos * tab.inv[dd];
        float c, sn; sincosf(ang, &sn, &c);
        int i1 = hh*DHH + dd, i2 = i1 + 32;
        float q1 = um[i1], q2 = um[i2];
        size_t qo = (((size_t)(b*NHH + hh))*SS + spos)*DHH;
        g_Q[qo + dd]      = q1*c - q2*sn;
        g_Q[qo + 32 + dd] = q2*c + q1*sn;
        float k1 = um[QKVD + i1] + (i1 < 256 ? kadd[i1] : 0.f);
        float k2 = um[QKVD + i2] + (i2 < 256 ? kadd[i2] : 0.f);
        size_t ko = (((size_t)(b*NHH + hh))*KVL + RG + spos)*DHH;
        g_K[ko + dd]      = k1*c - k2*sn;
        g_K[ko + 32 + dd] = k2*c + k1*sn;
    }
    for (int p = tid; p < QKVD; p += 256) {
        int hh = p >> 6;
        float vv = um[2*QKVD + p] + (p < 256 ? vadd[p] : 0.f);
        g_V[(((size_t)(b*NHH + hh))*KVS + RG + spos)*DHH + (p & 63)] = vv;
    }
}

// register tokens K/V fill + V pad-row zeroing
__global__ void regfill_kernel(const float* __restrict__ reg_k, const float* __restrict__ reg_v)
{
    int bh = blockIdx.x, hh = bh & 15;
    int j = threadIdx.x >> 6, d = threadIdx.x & 63;
    g_K[((size_t)bh*KVL + j)*DHH + d] = reg_k[((size_t)j*NHH + hh)*DHH + d];
    g_V[((size_t)bh*KVS + j)*DHH + d] = reg_v[((size_t)j*NHH + hh)*DHH + d];
    // zero V pad rows [KVL, KVS)
    for (int idx = threadIdx.x; idx < (KVS - KVL)*DHH; idx += blockDim.x)
        g_V[((size_t)bh*KVS + KVL)*DHH + idx] = 0.f;
}

// =======================================================================
// Kernel 4: scores = Q K^T / 8 + mask (TF32, 128x128 block, fused epilogue)
// =======================================================================
__global__ void __launch_bounds__(256) scores_tf32(const float* __restrict__ attn_mask)
{
    __shared__ float As[128*36];
    __shared__ float Bs[128*36];
    const int bh = blockIdx.z, b = bh >> 4, hh = bh & 15;
    const int tid = threadIdx.x;
    const int lane = tid & 31, wid = tid >> 5;
    const int g = lane >> 2, t = lane & 3;
    const int wm = (wid >> 2) * 64, wn = (wid & 3) * 32;
    const int bm = blockIdx.y * 128, bn = blockIdx.x * 128;
    const float* Ab = g_Q + (size_t)bh*SS*DHH;
    const float* Bb = g_K + (size_t)bh*KVL*DHH;

    float acc[4][4][4];
    #pragma unroll
    for (int mi = 0; mi < 4; mi++)
        #pragma unroll
        for (int ni = 0; ni < 4; ni++)
            #pragma unroll
            for (int e = 0; e < 4; e++) acc[mi][ni][e] = 0.f;

    #pragma unroll
    for (int k0 = 0; k0 < DHH; k0 += 32) {
        float4 av[4], bv[4];
        #pragma unroll
        for (int j = 0; j < 4; j++) {
            int idx = tid + j*256, r = idx >> 3, c4 = idx & 7;
            av[j] = *(const float4*)(Ab + (size_t)(bm + r)*DHH + k0 + c4*4);
            bv[j] = (bn + r < KVL)
                  ? *(const float4*)(Bb + (size_t)(bn + r)*DHH + k0 + c4*4)
                  : make_float4(0.f, 0.f, 0.f, 0.f);
        }
        __syncthreads();
        #pragma unroll
        for (int j = 0; j < 4; j++) {
            int idx = tid + j*256, r = idx >> 3, c4 = idx & 7;
            float* pa = As + r*36 + c4*4;
            pa[0] = cvtf(av[j].x); pa[1] = cvtf(av[j].y);
            pa[2] = cvtf(av[j].z); pa[3] = cvtf(av[j].w);
            float* pb = Bs + r*36 + c4*4;
            pb[0] = cvtf(bv[j].x); pb[1] = cvtf(bv[j].y);
            pb[2] = cvtf(bv[j].z); pb[3] = cvtf(bv[j].w);
        }
        __syncthreads();
        #pragma unroll
        for (int ks = 0; ks < 32; ks += 8) {
            unsigned a[4][4], bfr[4][2];
            #pragma unroll
            for (int mi = 0; mi < 4; mi++) {
                const float* p0 = As + (wm + mi*16 + g)*36 + ks;
                const float* p1 = p0 + 8*36;
                a[mi][0] = ldsu(p0 + t);
                a[mi][1] = ldsu(p1 + t);
                a[mi][2] = ldsu(p0 + t + 4);
                a[mi][3] = ldsu(p1 + t + 4);
            }
            #pragma unroll
            for (int ni = 0; ni < 4; ni++) {
                const float* pn = Bs + (wn + ni*8 + g)*36 + ks;
                bfr[ni][0] = ldsu(pn + t);
                bfr[ni][1] = ldsu(pn + t + 4);
            }
            #pragma unroll
            for (int mi = 0; mi < 4; mi++)
                #pragma unroll
                for (int ni = 0; ni < 4; ni++)
                    mma8(acc[mi][ni], a[mi], bfr[ni]);
        }
        __syncthreads();
    }

    #pragma unroll
    for (int mi = 0; mi < 4; mi++) {
        #pragma unroll
        for (int h = 0; h < 2; h++) {
            int gi = bm + wm + mi*16 + g + 8*h;
            float* sp = g_scores + ((size_t)bh*SS + gi)*KVS;
            const float* am = attn_mask + ((size_t)b*SS + gi)*SS;
            #pragma unroll
            for (int ni = 0; ni < 4; ni++) {
                int c0 = bn + wn + ni*8 + 2*t;
                #pragma unroll
                for (int e = 0; e < 2; e++) {
                    int gj = c0 + e;
                    if (gj < KVS) {
                        float outv;
                        if (gj >= KVL) outv = 0.f;
                        else {
                            float msk = 0.f;
                            if (gj >= RG) {
                                int js = gj - RG;
                                msk = am[js];
                                if (hh < NIAFH && js >= gi) msk += NEGV;
                            }
                            outv = 0.125f*acc[mi][ni][2*h + e] + msk;
                        }
                        sp[gj] = outv;
                    }
                }
            }
        }
    }
}

// =======================================================================
// Kernel 5: row softmax over 2056 keys, row cached in smem
// =======================================================================
__global__ void __launch_bounds__(256) softmax_kernel()
{
    __shared__ float row[KVL];      // 2056 floats
    __shared__ float red[8];
    __shared__ float bval;
    float* p = g_scores + (size_t)blockIdx.x*KVS;
    const int tid = threadIdx.x, lane = tid & 31, wid = tid >> 5;

    float mx = -3.4e38f;
    float4* r4 = (float4*)row;
    const float4* rd4 = (const float4*)p;
    float4* wr4 = (float4*)p;
    for (int j = tid; j < KVL/4; j += 256) {
        float4 v = rd4[j];
        r4[j] = v;
        mx = fmaxf(mx, fmaxf(fmaxf(v.x, v.y), fmaxf(v.z, v.w)));
    }
    #pragma unroll
    for (int o = 16; o; o >>= 1) mx = fmaxf(mx, __shfl_xor_sync(0xffffffffu, mx, o));
    if (lane == 0) red[wid] = mx;
    __syncthreads();
    if (tid == 0) {
        float m2 = red[0];
        for (int i = 1; i < 8; i++) m2 = fmaxf(m2, red[i]);
        bval = m2;
    }
    __syncthreads();
    mx = bval;

    float sum = 0.f;
    for (int j = tid; j < KVL; j += 256) {
        float e = __expf(row[j] - mx);
        row[j] = e;
        sum += e;
    }
    #pragma unroll
    for (int o = 16; o; o >>= 1) sum += __shfl_xor_sync(0xffffffffu, sum, o);
    if (lane == 0) red[wid] = sum;
    __syncthreads();
    if (tid == 0) {
        float s2 = 0.f;
        for (int i = 0; i < 8; i++) s2 += red[i];
        bval = 1.f / s2;
    }
    __syncthreads();
    float inv = bval;
    for (int j = tid; j < KVL/4; j += 256) {
        float4 v = r4[j];
        v.x *= inv; v.y *= inv; v.z *= inv; v.w *= inv;
        wr4[j] = v;
    }
}

// =======================================================================
// Kernel 6: attn_out = P @ V (TF32, 128x64 block, 4 warps), into g_down
// =======================================================================
__global__ void __launch_bounds__(128) pv_tf32()
{
    __shared__ float As[128*36];    // P tile [m][k]
    __shared__ float Vs[32*68];     // V tile [k][n]
    const int bh = blockIdx.z, b = bh >> 4, hh = bh & 15;
    const int tid = threadIdx.x;
    const int lane = tid & 31, wid = tid >> 5;
    const int g = lane >> 2, t = lane & 3;
    const int wm = (wid >> 1) * 64, wn = (wid & 1) * 32;
    const int bm = blockIdx.y * 128;
    const float* Pb = g_scores + (size_t)bh*SS*KVS;
    const float* Vb = g_V + (size_t)bh*KVS*DHH;

    float acc[4][4][4];
    #pragma unroll
    for (int mi = 0; mi < 4; mi++)
        #pragma unroll
        for (int ni = 0; ni < 4; ni++)
            #pragma unroll
            for (int e = 0; e < 4; e++) acc[mi][ni][e] = 0.f;

    for (int k0 = 0; k0 < KVS; k0 += 32) {
        float4 av[8], vv[4];
        #pragma unroll
        for (int j = 0; j < 8; j++) {
            int idx = tid + j*128, r = idx >> 3, c4 = idx & 7;
            av[j] = *(const float4*)(Pb + (size_t)(bm + r)*KVS + k0 + c4*4);
        }
        #pragma unroll
        for (int j = 0; j < 4; j++) {
            int idx = tid + j*128, k = idx >> 4, n4 = idx & 15;
            vv[j] = *(const float4*)(Vb + (size_t)(k0 + k)*DHH + n4*4);
        }
        __syncthreads();
        #pragma unroll
        for (int j = 0; j < 8; j++) {
            int idx = tid + j*128, r = idx >> 3, c4 = idx & 7;
            float* p = As + r*36 + c4*4;
            p[0] = cvtf(av[j].x); p[1] = cvtf(av[j].y);
            p[2] = cvtf(av[j].z); p[3] = cvtf(av[j].w);
        }
        #pragma unroll
        for (int j = 0; j < 4; j++) {
            int idx = tid + j*128, k = idx >> 4, n4 = idx & 15;
            float* p = Vs + k*68 + n4*4;
            p[0] = cvtf(vv[j].x); p[1] = cvtf(vv[j].y);
            p[2] = cvtf(vv[j].z); p[3] = cvtf(vv[j].w);
        }
        __syncthreads();
        #pragma unroll
        for (int ks = 0; ks < 32; ks += 8) {
            unsigned a[4][4], bfr[4][2];
            #pragma unroll
            for (int mi = 0; mi < 4; mi++) {
                const float* p0 = As + (wm + mi*16 + g)*36 + ks;
                const float* p1 = p0 + 8*36;
                a[mi][0] = ldsu(p0 + t);
                a[mi][1] = ldsu(p1 + t);
                a[mi][2] = ldsu(p0 + t + 4);
                a[mi][3] = ldsu(p1 + t + 4);
            }
            #pragma unroll
            for (int ni = 0; ni < 4; ni++) {
                int n = wn + ni*8 + g;
                bfr[ni][0] = ldsu(Vs + (ks + t)*68 + n);
                bfr[ni][1] = ldsu(Vs + (ks + t + 4)*68 + n);
            }
            #pragma unroll
            for (int mi = 0; mi < 4; mi++)
                #pragma unroll
                for (int ni = 0; ni < 4; ni++)
                    mma8(acc[mi][ni], a[mi], bfr[ni]);
        }
        __syncthreads();
    }

    #pragma unroll
    for (int mi = 0; mi < 4; mi++) {
        #pragma unroll
        for (int h = 0; h < 2; h++) {
            int gi = bm + wm + mi*16 + g + 8*h;
            int m = b*SS + gi;
            #pragma unroll
            for (int ni = 0; ni < 4; ni++) {
                int n = wn + ni*8 + 2*t;
                float2 v = make_float2(acc[mi][ni][2*h], acc[mi][ni][2*h + 1]);
                *(float2*)(g_down + (size_t)m*DWK + ZD + hh*DHH + n) = v;
            }
        }
    }
}

// =======================================================================
// Kernel 7: mlp = silu(gate)*val into g_down
// =======================================================================
__global__ void __launch_bounds__(256) mlp_kernel()
{
    size_t idx = (size_t)blockIdx.x*256 + threadIdx.x;
    int m = (int)(idx >> 12);
    int j = (int)(idx & 4095);
    float g = g_u[(size_t)m*UPN + 3*QKVD + j];
    float v = g_u[(size_t)m*UPN + 3*QKVD + MLPD + j];
    g_down[(size_t)m*DWK + ZD + QKVD + j] = g / (1.f + __expf(-g)) * v;
}

// =======================================================================
// launch
// =======================================================================
extern "C" void kernel_launch(void* const* d_in, const int* in_sizes, int n_in,
                              void* d_out, int out_size)
{
    const float* hs          = (const float*)d_in[0];
    const unsigned char* msk = (const unsigned char*)d_in[1];
    const float* noise       = (const float*)d_in[2];
    const float* next_noise  = (const float*)d_in[3];
    const float* attn_mask   = (const float*)d_in[4];
    const float* ln_w        = (const float*)d_in[5];
    const float* ln_b        = (const float*)d_in[6];
    const float* alpha       = (const float*)d_in[7];
    const float* iaf_wx      = (const float*)d_in[8];
    const float* iaf_wn      = (const float*)d_in[9];
    const float* iaf_w2      = (const float*)d_in[10];
    const float* up_w        = (const float*)d_in[11];
    const float* iaf_up_w    = (const float*)d_in[12];
    const float* down_w      = (const float*)d_in[13];
    const float* reg_k       = (const float*)d_in[14];
    const float* reg_v       = (const float*)d_in[15];
    float* out = (float*)d_out;

    float *p_xz, *p_u, *p_down;
    cudaGetSymbolAddress((void**)&p_xz, g_xz);
    cudaGetSymbolAddress((void**)&p_u, g_u);
    cudaGetSymbolAddress((void**)&p_down, g_down);

    const int GEMM_SMEM = (128*36 + 256*36) * 4;   // 55296
    (void)cudaFuncSetAttribute(tf32_gemm_nt<0>, cudaFuncAttributeMaxDynamicSharedMemorySize, GEMM_SMEM);
    (void)cudaFuncSetAttribute(tf32_gemm_nt<1>, cudaFuncAttributeMaxDynamicSharedMemorySize, GEMM_SMEM);

    RopeTab rt;
    for (int d = 0; d < 32; d++) {
        float pw = powf(10000.f, (float)(2*d) / 64.f);
        rt.inv[d] = 1.f / pw;
    }

    detect_mask_kernel<<<1, 32>>>(msk);

    token_kernel<<<NTOK/8, 128>>>(hs, msk, noise, ln_w, ln_b, iaf_wx, iaf_wn, iaf_w2, out);

    tf32_gemm_nt<0><<<dim3(UPN/256, NTOK/128), 256, GEMM_SMEM>>>(
        p_xz, up_w, p_u, NTOK, UPN, UPK, nullptr, nullptr);

    prep_qkv<<<NTOK, 256>>>(next_noise, iaf_up_w, rt);
    regfill_kernel<<<BB*NHH, 512>>>(reg_k, reg_v);

    scores_tf32<<<dim3((KVS + 127)/128, SS/128, BB*NHH), 256>>>(attn_mask);
    softmax_kernel<<<BB*NHH*SS, 256>>>();
    pv_tf32<<<dim3(1, SS/128, BB*NHH), 128>>>();

    mlp_kernel<<<(NTOK*MLPD)/256, 256>>>();

    tf32_gemm_nt<1><<<dim3(DD/256, NTOK/128), 256, GEMM_SMEM>>>(
        p_down, down_w, out, NTOK, DD, DWK, hs, alpha);
}

// round 9
// speedup vs baseline: 2.3748x; 1.3583x over previous
#include <cuda_runtime.h>
#include <math.h>

// ---------------- problem constants ----------------
#define BB 2
#define SS 2048
#define DD 1024
#define NHH 16
#define DHH 64
#define NIAFH 4
#define QKVD 1024
#define MLPD 4096
#define ZD 32
#define HIAFD 128
#define RG 8
#define KVL (SS + RG)          // 2056
#define KVS 2080               // padded V stride
#define UPN (QKVD + 2*QKVD + 2*MLPD)   // 11264
#define UPK (DD + ZD)          // 1056
#define DWK (ZD + QKVD + MLPD) // 5152
#define NTOK (BB*SS)           // 4096

#define ZSCALE 0.04419417382415922f    // sqrt(1/(32*16))
#define SPSHIFT 0.5413248546129181f    // log(e-1)
#define NEGV -1000000000.0f

// output layout: h_out | z | mu | sigma
#define OFF_Z  (NTOK*DD)
#define OFF_MU (OFF_Z + NTOK*ZD)
#define OFF_SG (OFF_MU + NTOK*ZD)

// ---------------- scratch ----------------
__device__ float g_xz[(size_t)NTOK*UPK];
__device__ float g_u[(size_t)NTOK*UPN];
__device__ float g_Q[(size_t)BB*NHH*SS*DHH];
__device__ float g_K[(size_t)BB*NHH*KVL*DHH];
__device__ float g_V[(size_t)BB*NHH*KVS*DHH];
__device__ float g_down[(size_t)NTOK*DWK];
__device__ int   g_mask_mode;

struct RopeTab { float inv[32]; };

// ---------------- tf32 mma helpers ----------------
__device__ __forceinline__ unsigned cvt_tf32(float x) {
    unsigned r;
    asm("cvt.rna.tf32.f32 %0, %1;" : "=r"(r) : "f"(x));
    return r;
}
__device__ __forceinline__ float cvtf(float x) { return __uint_as_float(cvt_tf32(x)); }

__device__ __forceinline__ void mma8(float* d, const unsigned* a, const unsigned* b) {
    asm volatile(
        "mma.sync.aligned.m16n8k8.row.col.f32.tf32.tf32.f32 "
        "{%0,%1,%2,%3}, {%4,%5,%6,%7}, {%8,%9}, {%0,%1,%2,%3};"
        : "+f"(d[0]), "+f"(d[1]), "+f"(d[2]), "+f"(d[3])
        : "r"(a[0]), "r"(a[1]), "r"(a[2]), "r"(a[3]), "r"(b[0]), "r"(b[1]));
}
__device__ __forceinline__ unsigned ldsu(const float* p) { return __float_as_uint(*p); }
__device__ __forceinline__ unsigned ldsc(const float* p) { return cvt_tf32(*p); }
__device__ __forceinline__ unsigned smem_u32(const void* p) {
    return (unsigned)__cvta_generic_to_shared(p);
}

// =======================================================================
// Kernel 0: classify the storage dtype of the bool `mask` input.
// =======================================================================
__global__ void detect_mask_kernel(const unsigned char* __restrict__ p)
{
    if (threadIdx.x != 0 || blockIdx.x != 0) return;
    const unsigned int* w = (const unsigned int*)p;
    bool allf = true, anyf = false, i32ok = true;
    for (int i = 0; i < 1024; i++) {
        unsigned int v = w[i];
        if (v == 0x3F800000u) anyf = true;
        else if (v != 0u) allf = false;
        if ((v & 0xFFFFFF00u) != 0u) i32ok = false;
    }
    g_mask_mode = (allf && anyf) ? 2 : (i32ok ? 1 : 0);
}

__device__ __forceinline__ float read_mask(const unsigned char* p, int m, int mode)
{
    if (mode == 1) return ((const int*)p)[m] != 0 ? 1.f : 0.f;
    if (mode == 2) return ((const float*)p)[m] != 0.f ? 1.f : 0.f;
    return p[m] != 0 ? 1.f : 0.f;
}

// =======================================================================
// Kernel 1: per-token LayerNorm + IAF encoder + z/mu/sigma (8 tokens/block)
// =======================================================================
__global__ void __launch_bounds__(128) token_kernel(
    const float* __restrict__ hs, const unsigned char* __restrict__ mask,
    const float* __restrict__ noise,
    const float* __restrict__ ln_w, const float* __restrict__ ln_b,
    const float* __restrict__ iaf_wx, const float* __restrict__ iaf_wn,
    const float* __restrict__ iaf_w2, float* __restrict__ out)
{
    __shared__ float xs[8][DD];
    __shared__ float ns[8][ZD];
    __shared__ float hdn[8][HIAFD];
    __shared__ float zps[8][2*ZD];
    __shared__ float fmv[8];
    __shared__ float redS[4], redQ[4], stat[2];

    const int tid = threadIdx.x, lane = tid & 31, wid = tid >> 5;
    const int m0 = blockIdx.x * 8;
    const int mmode = g_mask_mode;

    for (int idx = tid; idx < 8*ZD; idx += 128) {
        int t = idx >> 5, i = idx & 31;
        float fm = read_mask(mask, m0 + t, mmode);
        ns[t][i] = noise[(size_t)(m0 + t)*ZD + i] * fm;
        if (i == 0) fmv[t] = fm;
    }

    for (int t = 0; t < 8; t++) {
        const int m = m0 + t;
        const float* hp = hs + (size_t)m*DD;
        float s = 0.f, q = 0.f;
        #pragma unroll
        for (int k = 0; k < 8; k++) {
            float v = hp[tid + k*128];
            xs[t][tid + k*128] = v;
            s += v; q += v*v;
        }
        #pragma unroll
        for (int o = 16; o; o >>= 1) {
            s += __shfl_down_sync(0xffffffffu, s, o);
            q += __shfl_down_sync(0xffffffffu, q, o);
        }
        if (lane == 0) { redS[wid] = s; redQ[wid] = q; }
        __syncthreads();
        if (tid == 0) {
            float S1 = redS[0]+redS[1]+redS[2]+redS[3];
            float Q1 = redQ[0]+redQ[1]+redQ[2]+redQ[3];
            float mean = S1 / (float)DD;
            float var  = Q1 / (float)DD - mean*mean;
            stat[0] = mean;
            stat[1] = rsqrtf(var + 1e-5f);
        }
        __syncthreads();
        float mean = stat[0], rstd = stat[1];
        float* xzr = g_xz + (size_t)m*UPK;
        #pragma unroll
        for (int k = 0; k < 8; k++) {
            int d = tid + k*128;
            float x = (xs[t][d] - mean)*rstd*ln_w[d] + ln_b[d];
            xs[t][d] = x;
            xzr[d] = x;
        }
        __syncthreads();
    }

    {
        int j = tid;
        float acc[8];
        #pragma unroll
        for (int t = 0; t < 8; t++) acc[t] = 0.f;
        const float* wx = iaf_wx + (size_t)j*DD;
        for (int d = 0; d < DD; d++) {
            float w = wx[d];
            #pragma unroll
            for (int t = 0; t < 8; t++) acc[t] += xs[t][d]*w;
        }
        int dm = j % 31;
        const float* wn = iaf_wn + (size_t)j*ZD;
        for (int i = 0; i <= dm; i++) {
            float w = wn[i];
            #pragma unroll
            for (int t = 0; t < 8; t++) acc[t] += ns[t][i]*w;
        }
        #pragma unroll
        for (int t = 0; t < 8; t++) {
            float v = acc[t];
            hdn[t][j] = v / (1.f + __expf(-v));
        }
    }
    __syncthreads();

    if (tid < 64) {
        int o = tid, lim = o & 31;
        float acc[8];
        #pragma unroll
        for (int t = 0; t < 8; t++) acc[t] = 0.f;
        const float* w2 = iaf_w2 + (size_t)o*HIAFD;
        for (int j = 0; j < HIAFD; j++) {
            if ((j % 31) < lim) {
                float w = w2[j];
                #pragma unroll
                for (int t = 0; t < 8; t++) acc[t] += hdn[t][j]*w;
            }
        }
        #pragma unroll
        for (int t = 0; t < 8; t++) zps[t][o] = fmv[t]*ZSCALE*acc[t];
    }
    __syncthreads();

    for (int idx = tid; idx < 8*ZD; idx += 128) {
        int t = idx >> 5, i = idx & 31;
        int m = m0 + t;
        float mu = zps[t][i];
        float ls = zps[t][ZD + i] + SPSHIFT;
        float sg = (ls > 20.f) ? ls : log1pf(expf(ls));
        float z  = mu + sg*ns[t][i];
        g_xz[(size_t)m*UPK + DD + i] = z;
        g_down[(size_t)m*DWK + i]    = z;
        out[OFF_Z  + (size_t)m*ZD + i] = z;
        out[OFF_MU + (size_t)m*ZD + i] = mu;
        out[OFF_SG + (size_t)m*ZD + i] = sg;
    }
}

// =======================================================================
// Kernel 2: TF32 GEMM 128x256x32, cp.async double-buffered.
// =======================================================================
__device__ __forceinline__ void gemm_prefetch(
    const float* __restrict__ A, const float* __restrict__ B,
    float* As, float* Bs, int bm, int bn, int K, int k0, int tid)
{
    #pragma unroll
    for (int j = 0; j < 4; j++) {
        int idx = tid + j*256, r = idx >> 3, c4 = idx & 7;
        unsigned d = smem_u32(As + r*36 + c4*4);
        asm volatile("cp.async.ca.shared.global [%0], [%1], 16;"
                     :: "r"(d), "l"(A + (size_t)(bm + r)*K + k0 + c4*4));
    }
    #pragma unroll
    for (int j = 0; j < 8; j++) {
        int idx = tid + j*256, r = idx >> 3, c4 = idx & 7;
        unsigned d = smem_u32(Bs + r*36 + c4*4);
        asm volatile("cp.async.ca.shared.global [%0], [%1], 16;"
                     :: "r"(d), "l"(B + (size_t)(bn + r)*K + k0 + c4*4));
    }
}

template<int EPI>
__global__ void __launch_bounds__(256) tf32_gemm_nt(
    const float* __restrict__ A, const float* __restrict__ Bw, float* __restrict__ C,
    int M, int N, int K, const float* __restrict__ addsrc, const float* __restrict__ alphap)
{
    extern __shared__ float sm[];
    float* Asb[2] = { sm, sm + 128*36 };
    float* Bsb[2] = { sm + 2*128*36, sm + 2*128*36 + 256*36 };
    const int tid = threadIdx.x;
    const int lane = tid & 31, wid = tid >> 5;
    const int g = lane >> 2, t = lane & 3;
    const int wm = (wid >> 2) * 64, wn = (wid & 3) * 64;
    const int bm = blockIdx.y * 128, bn = blockIdx.x * 256;

    float acc[4][8][4];
    #pragma unroll
    for (int mi = 0; mi < 4; mi++)
        #pragma unroll
        for (int ni = 0; ni < 8; ni++)
            #pragma unroll
            for (int e = 0; e < 4; e++) acc[mi][ni][e] = 0.f;

    const int KT = K / 32;
    gemm_prefetch(A, Bw, Asb[0], Bsb[0], bm, bn, K, 0, tid);
    asm volatile("cp.async.commit_group;");

    for (int kt = 0; kt < KT; kt++) {
        const int buf = kt & 1;
        if (kt + 1 < KT) {
            gemm_prefetch(A, Bw, Asb[buf^1], Bsb[buf^1], bm, bn, K, (kt+1)*32, tid);
            asm volatile("cp.async.commit_group;");
            asm volatile("cp.async.wait_group 1;");
        } else {
            asm volatile("cp.async.wait_group 0;");
        }
        __syncthreads();
        const float* As = Asb[buf];
        const float* Bs = Bsb[buf];
        #pragma unroll
        for (int ks = 0; ks < 32; ks += 8) {
            unsigned a[4][4], b[8][2];
            #pragma unroll
            for (int mi = 0; mi < 4; mi++) {
                const float* p0 = As + (wm + mi*16 + g)*36 + ks;
                const float* p1 = p0 + 8*36;
                a[mi][0] = ldsc(p0 + t);
                a[mi][1] = ldsc(p1 + t);
                a[mi][2] = ldsc(p0 + t + 4);
                a[mi][3] = ldsc(p1 + t + 4);
            }
            #pragma unroll
            for (int ni = 0; ni < 8; ni++) {
                const float* pn = Bs + (wn + ni*8 + g)*36 + ks;
                b[ni][0] = ldsc(pn + t);
                b[ni][1] = ldsc(pn + t + 4);
            }
            #pragma unroll
            for (int mi = 0; mi < 4; mi++)
                #pragma unroll
                for (int ni = 0; ni < 8; ni++)
                    mma8(acc[mi][ni], a[mi], b[ni]);
        }
        __syncthreads();
    }

    float alpha = (EPI == 1) ? *alphap : 0.f;
    #pragma unroll
    for (int mi = 0; mi < 4; mi++) {
        int r0 = bm + wm + mi*16 + g;
        #pragma unroll
        for (int ni = 0; ni < 8; ni++) {
            int c0 = bn + wn + ni*8 + 2*t;
            #pragma unroll
            for (int h = 0; h < 2; h++) {
                int row = r0 + 8*h;
                size_t o = (size_t)row*N + c0;
                float v0 = acc[mi][ni][2*h], v1 = acc[mi][ni][2*h + 1];
                if (EPI == 1) {
                    v0 = addsrc[o]   + alpha*v0;
                    v1 = addsrc[o+1] + alpha*v1;
                }
                float2 v = make_float2(v0, v1);
                *(float2*)(C + o) = v;
            }
        }
    }
}

// =======================================================================
// Kernel 3: QKV prep — 8 tokens/block, weights amortized, RoPE
// =======================================================================
__global__ void __launch_bounds__(256) prep_qkv(
    const float* __restrict__ next_noise, const float* __restrict__ iaf_up_w, RopeTab tab)
{
    __shared__ float nn[8][ZD];
    __shared__ float kadds[8][256], vadds[8][256];
    const int tid = threadIdx.x;
    const int m0 = blockIdx.x * 8;

    {
        int t8 = tid >> 5, i = tid & 31;
        nn[t8][i] = next_noise[(size_t)(m0 + t8)*ZD + i];
    }
    __syncthreads();
    {
        const float* wk = iaf_up_w + (size_t)tid*ZD;
        const float* wv = iaf_up_w + (size_t)(QKVD + tid)*ZD;
        float ka[8], va[8];
        #pragma unroll
        for (int u = 0; u < 8; u++) { ka[u] = 0.f; va[u] = 0.f; }
        #pragma unroll 4
        for (int i = 0; i < ZD; i++) {
            float wki = wk[i], wvi = wv[i];
            #pragma unroll
            for (int u = 0; u < 8; u++) {
                ka[u] += nn[u][i]*wki;
                va[u] += nn[u][i]*wvi;
            }
        }
        #pragma unroll
        for (int u = 0; u < 8; u++) { kadds[u][tid] = ka[u]; vadds[u][tid] = va[u]; }
    }
    __syncthreads();

    const int dd = tid & 31;
    for (int u = 0; u < 8; u++) {
        int m = m0 + u;
        int b = m >> 11, spos = m & 2047;
        const float* um = g_u + (size_t)m*UPN;
        float ang = (float)spos * tab.inv[dd];
        float c, sn; sincosf(ang, &sn, &c);
        #pragma unroll
        for (int pp = 0; pp < 2; pp++) {
            int p = tid + pp*256;            // 0..511
            int hh = p >> 5;
            int i1 = hh*DHH + dd, i2 = i1 + 32;
            float q1 = um[i1], q2 = um[i2];
            size_t qo = (((size_t)(b*NHH + hh))*SS + spos)*DHH;
            g_Q[qo + dd]      = q1*c - q2*sn;
            g_Q[qo + 32 + dd] = q2*c + q1*sn;
            float k1 = um[QKVD + i1] + (i1 < 256 ? kadds[u][i1] : 0.f);
            float k2 = um[QKVD + i2] + (i2 < 256 ? kadds[u][i2] : 0.f);
            size_t ko = (((size_t)(b*NHH + hh))*KVL + RG + spos)*DHH;
            g_K[ko + dd]      = k1*c - k2*sn;
            g_K[ko + 32 + dd] = k2*c + k1*sn;
        }
        #pragma unroll
        for (int pp = 0; pp < 4; pp++) {
            int p = tid + pp*256;            // 0..1023
            int hh = p >> 6;
            float vv = um[2*QKVD + p] + (p < 256 ? vadds[u][p] : 0.f);
            g_V[(((size_t)(b*NHH + hh))*KVS + RG + spos)*DHH + (p & 63)] = vv;
        }
    }
}

// register tokens K/V fill + V pad-row zeroing
__global__ void regfill_kernel(const float* __restrict__ reg_k, const float* __restrict__ reg_v)
{
    int bh = blockIdx.x, hh = bh & 15;
    int j = threadIdx.x >> 6, d = threadIdx.x & 63;
    g_K[((size_t)bh*KVL + j)*DHH + d] = reg_k[((size_t)j*NHH + hh)*DHH + d];
    g_V[((size_t)bh*KVS + j)*DHH + d] = reg_v[((size_t)j*NHH + hh)*DHH + d];
    for (int idx = threadIdx.x; idx < (KVS - KVL)*DHH; idx += blockDim.x)
        g_V[((size_t)bh*KVS + KVL)*DHH + idx] = 0.f;
}

// =======================================================================
// Kernel 4: FLASH attention (fused QK^T + online softmax + PV)
// =======================================================================
#define KSP 68
#define VSP 72
#define FLASH_SMEM ((128*KSP + 128*VSP)*4)

__global__ void __launch_bounds__(256) flash_kernel(const float* __restrict__ attn_mask)
{
    extern __shared__ float sf[];
    float* Ks = sf;
    float* Vs = sf + 128*KSP;
    const int tid = threadIdx.x, lane = tid & 31, w = tid >> 5;
    const int g = lane >> 2, t = lane & 3;
    const int bh = blockIdx.y, b = bh >> 4, hh = bh & 15;
    const int bm = blockIdx.x * 128;
    const float* Qb = g_Q + (size_t)bh*SS*DHH;
    const float* Kb = g_K + (size_t)bh*KVL*DHH;
    const float* Vb = g_V + (size_t)bh*KVS*DHH;

    #pragma unroll
    for (int j = 0; j < 8; j++) {
        int idx = tid + j*256;
        int r = idx >> 4, c4 = idx & 15;
        float4 q = *(const float4*)(Qb + (size_t)(bm + r)*DHH + c4*4);
        float* p = Ks + r*KSP + c4*4;
        p[0]=cvtf(q.x); p[1]=cvtf(q.y); p[2]=cvtf(q.z); p[3]=cvtf(q.w);
    }
    __syncthreads();
    unsigned aQ[8][4];
    #pragma unroll
    for (int k = 0; k < 8; k++) {
        const float* p0 = Ks + (w*16 + g)*KSP + k*8;
        const float* p1 = p0 + 8*KSP;
        aQ[k][0] = ldsu(p0 + t);
        aQ[k][1] = ldsu(p1 + t);
        aQ[k][2] = ldsu(p0 + t + 4);
        aQ[k][3] = ldsu(p1 + t + 4);
    }
    __syncthreads();

    float accO[8][4];
    #pragma unroll
    for (int vn = 0; vn < 8; vn++)
        #pragma unroll
        for (int e = 0; e < 4; e++) accO[vn][e] = 0.f;
    float mrow0 = -1e30f, mrow1 = -1e30f, lrow0 = 0.f, lrow1 = 0.f;

    const int gi0 = bm + w*16 + g, gi1 = gi0 + 8;
    const float* am0 = attn_mask + ((size_t)b*SS + gi0)*SS;
    const float* am1 = attn_mask + ((size_t)b*SS + gi1)*SS;
    const bool iafh = (hh < NIAFH);

    for (int j0 = 0; j0 < KVL; j0 += 128) {
        #pragma unroll
        for (int j = 0; j < 8; j++) {
            int idx = tid + j*256;
            int r = idx >> 4, c4 = idx & 15;
            bool ok = (j0 + r) < KVL;
            float4 kv = ok ? *(const float4*)(Kb + (size_t)(j0 + r)*DHH + c4*4)
                           : make_float4(0.f,0.f,0.f,0.f);
            float* pk = Ks + r*KSP + c4*4;
            pk[0]=cvtf(kv.x); pk[1]=cvtf(kv.y); pk[2]=cvtf(kv.z); pk[3]=cvtf(kv.w);
            float4 vv = ok ? *(const float4*)(Vb + (size_t)(j0 + r)*DHH + c4*4)
                           : make_float4(0.f,0.f,0.f,0.f);
            float* pv = Vs + r*VSP + c4*4;
            pv[0]=cvtf(vv.x); pv[1]=cvtf(vv.y); pv[2]=cvtf(vv.z); pv[3]=cvtf(vv.w);
        }
        __syncthreads();

        float s[16][4];
        #pragma unroll
        for (int nt = 0; nt < 16; nt++)
            #pragma unroll
            for (int e = 0; e < 4; e++) s[nt][e] = 0.f;
        #pragma unroll
        for (int ks = 0; ks < 8; ks++) {
            #pragma unroll
            for (int nt = 0; nt < 16; nt++) {
                unsigned bb[2];
                const float* pn = Ks + (nt*8 + g)*KSP + ks*8;
                bb[0] = ldsu(pn + t);
                bb[1] = ldsu(pn + t + 4);
                mma8(s[nt], aQ[ks], bb);
            }
        }

        float tmax0 = -1e30f, tmax1 = -1e30f;
        #pragma unroll
        for (int nt = 0; nt < 16; nt++) {
            int colbase = j0 + nt*8;
            if (colbase >= KVL) {
                s[nt][0] = s[nt][1] = s[nt][2] = s[nt][3] = -1e30f;
            } else if (colbase < RG) {
                s[nt][0] *= 0.125f; s[nt][1] *= 0.125f;
                s[nt][2] *= 0.125f; s[nt][3] *= 0.125f;
            } else {
                int js = colbase + 2*t - RG;
                float2 a0 = *(const float2*)(am0 + js);
                float2 a1 = *(const float2*)(am1 + js);
                float mk00 = a0.x, mk01 = a0.y, mk10 = a1.x, mk11 = a1.y;
                if (iafh) {
                    if (js     >= gi0) mk00 += NEGV;
                    if (js + 1 >= gi0) mk01 += NEGV;
                    if (js     >= gi1) mk10 += NEGV;
                    if (js + 1 >= gi1) mk11 += NEGV;
                }
                s[nt][0] = s[nt][0]*0.125f + mk00;
                s[nt][1] = s[nt][1]*0.125f + mk01;
                s[nt][2] = s[nt][2]*0.125f + mk10;
                s[nt][3] = s[nt][3]*0.125f + mk11;
            }
            tmax0 = fmaxf(tmax0, fmaxf(s[nt][0], s[nt][1]));
            tmax1 = fmaxf(tmax1, fmaxf(s[nt][2], s[nt][3]));
        }
        tmax0 = fmaxf(tmax0, __shfl_xor_sync(0xffffffffu, tmax0, 1));
        tmax0 = fmaxf(tmax0, __shfl_xor_sync(0xffffffffu, tmax0, 2));
        tmax1 = fmaxf(tmax1, __shfl_xor_sync(0xffffffffu, tmax1, 1));
        tmax1 = fmaxf(tmax1, __shfl_xor_sync(0xffffffffu, tmax1, 2));

        float newm0 = fmaxf(mrow0, tmax0);
        float newm1 = fmaxf(mrow1, tmax1);
        float sc0 = __expf(mrow0 - newm0);
        float sc1 = __expf(mrow1 - newm1);
        float rs0 = 0.f, rs1 = 0.f;
        #pragma unroll
        for (int nt = 0; nt < 16; nt++) {
            float p0 = __expf(s[nt][0] - newm0);
            float p1 = __expf(s[nt][1] - newm0);
            float p2 = __expf(s[nt][2] - newm1);
            float p3 = __expf(s[nt][3] - newm1);
            s[nt][0] = p0; s[nt][1] = p1; s[nt][2] = p2; s[nt][3] = p3;
            rs0 += p0 + p1; rs1 += p2 + p3;
        }
        rs0 += __shfl_xor_sync(0xffffffffu, rs0, 1);
        rs0 += __shfl_xor_sync(0xffffffffu, rs0, 2);
        rs1 += __shfl_xor_sync(0xffffffffu, rs1, 1);
        rs1 += __shfl_xor_sync(0xffffffffu, rs1, 2);
        lrow0 = lrow0*sc0 + rs0;
        lrow1 = lrow1*sc1 + rs1;
        mrow0 = newm0; mrow1 = newm1;
        #pragma unroll
        for (int vn = 0; vn < 8; vn++) {
            accO[vn][0] *= sc0; accO[vn][1] *= sc0;
            accO[vn][2] *= sc1; accO[vn][3] *= sc1;
        }

        const int qb = lane & ~3;
        const int s0l = qb + (t >> 1), s1l = s0l + 2;
        const bool odd = (t & 1);
        #pragma unroll
        for (int ks = 0; ks < 16; ks++) {
            float x0 = __shfl_sync(0xffffffffu, s[ks][0], s0l);
            float x1 = __shfl_sync(0xffffffffu, s[ks][1], s0l);
            float y0 = __shfl_sync(0xffffffffu, s[ks][2], s0l);
            float y1 = __shfl_sync(0xffffffffu, s[ks][3], s0l);
            float x0b = __shfl_sync(0xffffffffu, s[ks][0], s1l);
            float x1b = __shfl_sync(0xffffffffu, s[ks][1], s1l);
            float y0b = __shfl_sync(0xffffffffu, s[ks][2], s1l);
            float y1b = __shfl_sync(0xffffffffu, s[ks][3], s1l);
            unsigned aP[4];
            aP[0] = cvt_tf32(odd ? x1  : x0);
            aP[1] = cvt_tf32(odd ? y1  : y0);
            aP[2] = cvt_tf32(odd ? x1b : x0b);
            aP[3] = cvt_tf32(odd ? y1b : y0b);
            #pragma unroll
            for (int vn = 0; vn < 8; vn++) {
                unsigned bb[2];
                bb[0] = ldsu(Vs + (ks*8 + t)*VSP + vn*8 + g);
                bb[1] = ldsu(Vs + (ks*8 + t + 4)*VSP + vn*8 + g);
                mma8(accO[vn], aP, bb);
            }
        }
        __syncthreads();
    }

    float inv0 = 1.f / lrow0, inv1 = 1.f / lrow1;
    int row0 = b*SS + gi0, row1 = b*SS + gi1;
    #pragma unroll
    for (int vn = 0; vn < 8; vn++) {
        int n = vn*8 + 2*t;
        float2 v0 = make_float2(accO[vn][0]*inv0, accO[vn][1]*inv0);
        *(float2*)(g_down + (size_t)row0*DWK + ZD + hh*DHH + n) = v0;
        float2 v1 = make_float2(accO[vn][2]*inv1, accO[vn][3]*inv1);
        *(float2*)(g_down + (size_t)row1*DWK + ZD + hh*DHH + n) = v1;
    }
}

// =======================================================================
// Kernel 5: mlp = silu(gate)*val into g_down
// =======================================================================
__global__ void __launch_bounds__(256) mlp_kernel()
{
    size_t idx = (size_t)blockIdx.x*256 + threadIdx.x;
    int m = (int)(idx >> 12);
    int j = (int)(idx & 4095);
    float g = g_u[(size_t)m*UPN + 3*QKVD + j];
    float v = g_u[(size_t)m*UPN + 3*QKVD + MLPD + j];
    g_down[(size_t)m*DWK + ZD + QKVD + j] = g / (1.f + __expf(-g)) * v;
}

// =======================================================================
// launch
// =======================================================================
extern "C" void kernel_launch(void* const* d_in, const int* in_sizes, int n_in,
                              void* d_out, int out_size)
{
    const float* hs          = (const float*)d_in[0];
    const unsigned char* msk = (const unsigned char*)d_in[1];
    const float* noise       = (const float*)d_in[2];
    const float* next_noise  = (const float*)d_in[3];
    const float* attn_mask   = (const float*)d_in[4];
    const float* ln_w        = (const float*)d_in[5];
    const float* ln_b        = (const float*)d_in[6];
    const float* alpha       = (const float*)d_in[7];
    const float* iaf_wx      = (const float*)d_in[8];
    const float* iaf_wn      = (const float*)d_in[9];
    const float* iaf_w2      = (const float*)d_in[10];
    const float* up_w        = (const float*)d_in[11];
    const float* iaf_up_w    = (const float*)d_in[12];
    const float* down_w      = (const float*)d_in[13];
    const float* reg_k       = (const float*)d_in[14];
    const float* reg_v       = (const float*)d_in[15];
    float* out = (float*)d_out;

    float *p_xz, *p_u, *p_down;
    cudaGetSymbolAddress((void**)&p_xz, g_xz);
    cudaGetSymbolAddress((void**)&p_u, g_u);
    cudaGetSymbolAddress((void**)&p_down, g_down);

    const int GEMM_SMEM = (2*128 + 2*256)*36*4;   // 110592
    (void)cudaFuncSetAttribute(tf32_gemm_nt<0>, cudaFuncAttributeMaxDynamicSharedMemorySize, GEMM_SMEM);
    (void)cudaFuncSetAttribute(tf32_gemm_nt<1>, cudaFuncAttributeMaxDynamicSharedMemorySize, GEMM_SMEM);
    (void)cudaFuncSetAttribute(flash_kernel, cudaFuncAttributeMaxDynamicSharedMemorySize, FLASH_SMEM);

    RopeTab rt;
    for (int d = 0; d < 32; d++) {
        float pw = powf(10000.f, (float)(2*d) / 64.f);
        rt.inv[d] = 1.f / pw;
    }

    detect_mask_kernel<<<1, 32>>>(msk);

    token_kernel<<<NTOK/8, 128>>>(hs, msk, noise, ln_w, ln_b, iaf_wx, iaf_wn, iaf_w2, out);

    tf32_gemm_nt<0><<<dim3(UPN/256, NTOK/128), 256, GEMM_SMEM>>>(
        p_xz, up_w, p_u, NTOK, UPN, UPK, nullptr, nullptr);

    prep_qkv<<<NTOK/8, 256>>>(next_noise, iaf_up_w, rt);
    regfill_kernel<<<BB*NHH, 512>>>(reg_k, reg_v);

    flash_kernel<<<dim3(SS/128, BB*NHH), 256, FLASH_SMEM>>>(attn_mask);

    mlp_kernel<<<(NTOK*MLPD)/256, 256>>>();

    tf32_gemm_nt<1><<<dim3(DD/256, NTOK/128), 256, GEMM_SMEM>>>(
        p_down, down_w, out, NTOK, DD, DWK, hs, alpha);
}

// round 11
// speedup vs baseline: 3.2047x; 1.3495x over previous
#include <cuda_runtime.h>
#include <cuda_bf16.h>
#include <math.h>

// ---------------- problem constants ----------------
#define BB 2
#define SS 2048
#define DD 1024
#define NHH 16
#define DHH 64
#define NIAFH 4
#define QKVD 1024
#define MLPD 4096
#define ZD 32
#define HIAFD 128
#define RG 8
#define KVL (SS + RG)          // 2056
#define KVS 2080               // padded V stride
#define UPN (QKVD + 2*QKVD + 2*MLPD)   // 11264
#define UPK (DD + ZD)          // 1056
#define DWK (ZD + QKVD + MLPD) // 5152
#define NTOK (BB*SS)           // 4096

#define ZSCALE 0.04419417382415922f    // sqrt(1/(32*16))
#define SPSHIFT 0.5413248546129181f    // log(e-1)
#define NEGV -1000000000.0f

// output layout: h_out | z | mu | sigma
#define OFF_Z  (NTOK*DD)
#define OFF_MU (OFF_Z + NTOK*ZD)
#define OFF_SG (OFF_MU + NTOK*ZD)

// ---------------- scratch ----------------
__device__ __nv_bfloat16 g_xz_b[(size_t)NTOK*UPK];     // [x | z] bf16
__device__ __nv_bfloat16 g_u_b[(size_t)NTOK*UPN];      // up-proj out bf16
__device__ __nv_bfloat16 g_down_b[(size_t)NTOK*DWK];   // [z|attn|mlp] bf16
__device__ __nv_bfloat16 g_upw_b[(size_t)UPN*UPK];     // bf16 up weights
__device__ __nv_bfloat16 g_dnw_b[(size_t)DD*DWK];      // bf16 down weights
__device__ float g_Q[(size_t)BB*NHH*SS*DHH];
__device__ float g_K[(size_t)BB*NHH*KVL*DHH];
__device__ float g_V[(size_t)BB*NHH*KVS*DHH];
__device__ int   g_mask_mode;

struct RopeTab { float inv[32]; };

// ---------------- mma helpers ----------------
__device__ __forceinline__ unsigned cvt_tf32(float x) {
    unsigned r;
    asm("cvt.rna.tf32.f32 %0, %1;" : "=r"(r) : "f"(x));
    return r;
}
__device__ __forceinline__ float cvtf(float x) { return __uint_as_float(cvt_tf32(x)); }

__device__ __forceinline__ void mma8(float* d, const unsigned* a, const unsigned* b) {
    asm volatile(
        "mma.sync.aligned.m16n8k8.row.col.f32.tf32.tf32.f32 "
        "{%0,%1,%2,%3}, {%4,%5,%6,%7}, {%8,%9}, {%0,%1,%2,%3};"
        : "+f"(d[0]), "+f"(d[1]), "+f"(d[2]), "+f"(d[3])
        : "r"(a[0]), "r"(a[1]), "r"(a[2]), "r"(a[3]), "r"(b[0]), "r"(b[1]));
}
__device__ __forceinline__ void mma16bf(float* d, const unsigned* a, const unsigned* b) {
    asm volatile(
        "mma.sync.aligned.m16n8k16.row.col.f32.bf16.bf16.f32 "
        "{%0,%1,%2,%3}, {%4,%5,%6,%7}, {%8,%9}, {%0,%1,%2,%3};"
        : "+f"(d[0]), "+f"(d[1]), "+f"(d[2]), "+f"(d[3])
        : "r"(a[0]), "r"(a[1]), "r"(a[2]), "r"(a[3]), "r"(b[0]), "r"(b[1]));
}
__device__ __forceinline__ unsigned ldsu(const float* p) { return __float_as_uint(*p); }
__device__ __forceinline__ unsigned smem_u32(const void* p) {
    return (unsigned)__cvta_generic_to_shared(p);
}

// =======================================================================
// Kernel 0: classify the storage dtype of the bool `mask` input.
// =======================================================================
__global__ void detect_mask_kernel(const unsigned char* __restrict__ p)
{
    if (threadIdx.x != 0 || blockIdx.x != 0) return;
    const unsigned int* w = (const unsigned int*)p;
    bool allf = true, anyf = false, i32ok = true;
    for (int i = 0; i < 1024; i++) {
        unsigned int v = w[i];
        if (v == 0x3F800000u) anyf = true;
        else if (v != 0u) allf = false;
        if ((v & 0xFFFFFF00u) != 0u) i32ok = false;
    }
    g_mask_mode = (allf && anyf) ? 2 : (i32ok ? 1 : 0);
}

__device__ __forceinline__ float read_mask(const unsigned char* p, int m, int mode)
{
    if (mode == 1) return ((const int*)p)[m] != 0 ? 1.f : 0.f;
    if (mode == 2) return ((const float*)p)[m] != 0.f ? 1.f : 0.f;
    return p[m] != 0 ? 1.f : 0.f;
}

// =======================================================================
// Kernel 0b: fp32 -> bf16 weight conversion (pairs)
// =======================================================================
__global__ void convert_bf16_kernel(const float* __restrict__ src,
                                    __nv_bfloat16* __restrict__ dst, int n2)
{
    int i = blockIdx.x*256 + threadIdx.x;
    if (i < n2) {
        float2 v = ((const float2*)src)[i];
        ((__nv_bfloat162*)dst)[i] = __floats2bfloat162_rn(v.x, v.y);
    }
}

// =======================================================================
// Kernel 1: per-token LayerNorm + IAF encoder + z/mu/sigma (8 tokens/block)
// =======================================================================
__global__ void __launch_bounds__(128) token_kernel(
    const float* __restrict__ hs, const unsigned char* __restrict__ mask,
    const float* __restrict__ noise,
    const float* __restrict__ ln_w, const float* __restrict__ ln_b,
    const float* __restrict__ iaf_wx, const float* __restrict__ iaf_wn,
    const float* __restrict__ iaf_w2, float* __restrict__ out)
{
    __shared__ float xs[8][DD];
    __shared__ float ns[8][ZD];
    __shared__ float hdn[8][HIAFD];
    __shared__ float zps[8][2*ZD];
    __shared__ float fmv[8];
    __shared__ float redS[4], redQ[4], stat[2];

    const int tid = threadIdx.x, lane = tid & 31, wid = tid >> 5;
    const int m0 = blockIdx.x * 8;
    const int mmode = g_mask_mode;

    for (int idx = tid; idx < 8*ZD; idx += 128) {
        int t = idx >> 5, i = idx & 31;
        float fm = read_mask(mask, m0 + t, mmode);
        ns[t][i] = noise[(size_t)(m0 + t)*ZD + i] * fm;
        if (i == 0) fmv[t] = fm;
    }

    for (int t = 0; t < 8; t++) {
        const int m = m0 + t;
        const float* hp = hs + (size_t)m*DD;
        float s = 0.f, q = 0.f;
        #pragma unroll
        for (int k = 0; k < 8; k++) {
            float v = hp[tid + k*128];
            xs[t][tid + k*128] = v;
            s += v; q += v*v;
        }
        #pragma unroll
        for (int o = 16; o; o >>= 1) {
            s += __shfl_down_sync(0xffffffffu, s, o);
            q += __shfl_down_sync(0xffffffffu, q, o);
        }
        if (lane == 0) { redS[wid] = s; redQ[wid] = q; }
        __syncthreads();
        if (tid == 0) {
            float S1 = redS[0]+redS[1]+redS[2]+redS[3];
            float Q1 = redQ[0]+redQ[1]+redQ[2]+redQ[3];
            float mean = S1 / (float)DD;
            float var  = Q1 / (float)DD - mean*mean;
            stat[0] = mean;
            stat[1] = rsqrtf(var + 1e-5f);
        }
        __syncthreads();
        float mean = stat[0], rstd = stat[1];
        __nv_bfloat16* xzr = g_xz_b + (size_t)m*UPK;
        #pragma unroll
        for (int k = 0; k < 8; k++) {
            int d = tid + k*128;
            float x = (xs[t][d] - mean)*rstd*ln_w[d] + ln_b[d];
            xs[t][d] = x;
            xzr[d] = __float2bfloat16(x);
        }
        __syncthreads();
    }

    {
        int j = tid;
        float acc[8];
        #pragma unroll
        for (int t = 0; t < 8; t++) acc[t] = 0.f;
        const float* wx = iaf_wx + (size_t)j*DD;
        for (int d = 0; d < DD; d++) {
            float w = wx[d];
            #pragma unroll
            for (int t = 0; t < 8; t++) acc[t] += xs[t][d]*w;
        }
        int dm = j % 31;
        const float* wn = iaf_wn + (size_t)j*ZD;
        for (int i = 0; i <= dm; i++) {
            float w = wn[i];
            #pragma unroll
            for (int t = 0; t < 8; t++) acc[t] += ns[t][i]*w;
        }
        #pragma unroll
        for (int t = 0; t < 8; t++) {
            float v = acc[t];
            hdn[t][j] = v / (1.f + __expf(-v));
        }
    }
    __syncthreads();

    if (tid < 64) {
        int o = tid, lim = o & 31;
        float acc[8];
        #pragma unroll
        for (int t = 0; t < 8; t++) acc[t] = 0.f;
        const float* w2 = iaf_w2 + (size_t)o*HIAFD;
        for (int j = 0; j < HIAFD; j++) {
            if ((j % 31) < lim) {
                float w = w2[j];
                #pragma unroll
                for (int t = 0; t < 8; t++) acc[t] += hdn[t][j]*w;
            }
        }
        #pragma unroll
        for (int t = 0; t < 8; t++) zps[t][o] = fmv[t]*ZSCALE*acc[t];
    }
    __syncthreads();

    for (int idx = tid; idx < 8*ZD; idx += 128) {
        int t = idx >> 5, i = idx & 31;
        int m = m0 + t;
        float mu = zps[t][i];
        float ls = zps[t][ZD + i] + SPSHIFT;
        float sg = (ls > 20.f) ? ls : log1pf(expf(ls));
        float z  = mu + sg*ns[t][i];
        g_xz_b[(size_t)m*UPK + DD + i] = __float2bfloat16(z);
        g_down_b[(size_t)m*DWK + i]    = __float2bfloat16(z);
        out[OFF_Z  + (size_t)m*ZD + i] = z;
        out[OFF_MU + (size_t)m*ZD + i] = mu;
        out[OFF_SG + (size_t)m*ZD + i] = sg;
    }
}

// =======================================================================
// Kernel 2: BF16 GEMM 128x256x32, cp.async double-buffered, m16n8k16.
//   A[M][K] bf16, B[N][K] bf16.  EPI=0: C bf16;  EPI=1: C fp32 = addsrc+alpha*acc
//   smem: 2*(128+256)*40*2 = 61440 B dynamic
// =======================================================================
#define APITCH 40

__device__ __forceinline__ void bgemm_prefetch(
    const __nv_bfloat16* __restrict__ A, const __nv_bfloat16* __restrict__ B,
    __nv_bfloat16* As, __nv_bfloat16* Bs, int bm, int bn, int K, int k0, int tid)
{
    #pragma unroll
    for (int j = 0; j < 2; j++) {
        int idx = tid + j*256, r = idx >> 2, c = idx & 3;
        unsigned d = smem_u32(As + r*APITCH + c*8);
        asm volatile("cp.async.ca.shared.global [%0], [%1], 16;"
                     :: "r"(d), "l"(A + (size_t)(bm + r)*K + k0 + c*8));
    }
    #pragma unroll
    for (int j = 0; j < 4; j++) {
        int idx = tid + j*256, r = idx >> 2, c = idx & 3;
        unsigned d = smem_u32(Bs + r*APITCH + c*8);
        asm volatile("cp.async.ca.shared.global [%0], [%1], 16;"
                     :: "r"(d), "l"(B + (size_t)(bn + r)*K + k0 + c*8));
    }
}

template<int EPI>
__global__ void __launch_bounds__(256) bf16_gemm_nt(
    const __nv_bfloat16* __restrict__ A, const __nv_bfloat16* __restrict__ Bw, void* Cp,
    int M, int N, int K, const float* __restrict__ addsrc, const float* __restrict__ alphap)
{
    extern __shared__ __nv_bfloat16 smb[];
    __nv_bfloat16* Asb[2] = { smb, smb + 128*APITCH };
    __nv_bfloat16* Bsb[2] = { smb + 2*128*APITCH, smb + 2*128*APITCH + 256*APITCH };
    const int tid = threadIdx.x;
    const int lane = tid & 31, wid = tid >> 5;
    const int g = lane >> 2, t = lane & 3;
    const int wm = (wid >> 2) * 64, wn = (wid & 3) * 64;
    const int bm = blockIdx.y * 128, bn = blockIdx.x * 256;

    float acc[4][8][4];
    #pragma unroll
    for (int mi = 0; mi < 4; mi++)
        #pragma unroll
        for (int ni = 0; ni < 8; ni++)
            #pragma unroll
            for (int e = 0; e < 4; e++) acc[mi][ni][e] = 0.f;

    const int KT = K / 32;
    bgemm_prefetch(A, Bw, Asb[0], Bsb[0], bm, bn, K, 0, tid);
    asm volatile("cp.async.commit_group;");

    for (int kt = 0; kt < KT; kt++) {
        const int buf = kt & 1;
        if (kt + 1 < KT) {
            bgemm_prefetch(A, Bw, Asb[buf^1], Bsb[buf^1], bm, bn, K, (kt+1)*32, tid);
            asm volatile("cp.async.commit_group;");
            asm volatile("cp.async.wait_group 1;");
        } else {
            asm volatile("cp.async.wait_group 0;");
        }
        __syncthreads();
        const __nv_bfloat16* As = Asb[buf];
        const __nv_bfloat16* Bs = Bsb[buf];
        #pragma unroll
        for (int ks = 0; ks < 32; ks += 16) {
            unsigned a[4][4], b[8][2];
            #pragma unroll
            for (int mi = 0; mi < 4; mi++) {
                const __nv_bfloat16* p0 = As + (wm + mi*16 + g)*APITCH + ks + 2*t;
                a[mi][0] = *(const unsigned*)(p0);
                a[mi][1] = *(const unsigned*)(p0 + 8*APITCH);
                a[mi][2] = *(const unsigned*)(p0 + 8);
                a[mi][3] = *(const unsigned*)(p0 + 8*APITCH + 8);
            }
            #pragma unroll
            for (int ni = 0; ni < 8; ni++) {
                const __nv_bfloat16* pn = Bs + (wn + ni*8 + g)*APITCH + ks + 2*t;
                b[ni][0] = *(const unsigned*)(pn);
                b[ni][1] = *(const unsigned*)(pn + 8);
            }
            #pragma unroll
            for (int mi = 0; mi < 4; mi++)
                #pragma unroll
                for (int ni = 0; ni < 8; ni++)
                    mma16bf(acc[mi][ni], a[mi], b[ni]);
        }
        __syncthreads();
    }

    float alpha = (EPI == 1) ? *alphap : 0.f;
    #pragma unroll
    for (int mi = 0; mi < 4; mi++) {
        int r0 = bm + wm + mi*16 + g;
        #pragma unroll
        for (int ni = 0; ni < 8; ni++) {
            int c0 = bn + wn + ni*8 + 2*t;
            #pragma unroll
            for (int h = 0; h < 2; h++) {
                int row = r0 + 8*h;
                size_t o = (size_t)row*N + c0;
                float v0 = acc[mi][ni][2*h], v1 = acc[mi][ni][2*h + 1];
                if (EPI == 1) {
                    float* C = (float*)Cp;
                    C[o]   = addsrc[o]   + alpha*v0;
                    C[o+1] = addsrc[o+1] + alpha*v1;
                } else {
                    __nv_bfloat16* C = (__nv_bfloat16*)Cp;
                    *(__nv_bfloat162*)(C + o) = __floats2bfloat162_rn(v0, v1);
                }
            }
        }
    }
}

// =======================================================================
// Kernel 3: QKV prep — 8 tokens/block, bf16 u reads, RoPE, fp32 QKV out
// =======================================================================
__global__ void __launch_bounds__(256) prep_qkv(
    const float* __restrict__ next_noise, const float* __restrict__ iaf_up_w, RopeTab tab)
{
    __shared__ float nn[8][ZD];
    __shared__ float kadds[8][256], vadds[8][256];
    const int tid = threadIdx.x;
    const int m0 = blockIdx.x * 8;

    {
        int t8 = tid >> 5, i = tid & 31;
        nn[t8][i] = next_noise[(size_t)(m0 + t8)*ZD + i];
    }
    __syncthreads();
    {
        const float* wk = iaf_up_w + (size_t)tid*ZD;
        const float* wv = iaf_up_w + (size_t)(QKVD + tid)*ZD;
        float ka[8], va[8];
        #pragma unroll
        for (int u = 0; u < 8; u++) { ka[u] = 0.f; va[u] = 0.f; }
        #pragma unroll 4
        for (int i = 0; i < ZD; i++) {
            float wki = wk[i], wvi = wv[i];
            #pragma unroll
            for (int u = 0; u < 8; u++) {
                ka[u] += nn[u][i]*wki;
                va[u] += nn[u][i]*wvi;
            }
        }
        #pragma unroll
        for (int u = 0; u < 8; u++) { kadds[u][tid] = ka[u]; vadds[u][tid] = va[u]; }
    }
    __syncthreads();

    const int dd = tid & 31;
    for (int u = 0; u < 8; u++) {
        int m = m0 + u;
        int b = m >> 11, spos = m & 2047;
        const __nv_bfloat16* um = g_u_b + (size_t)m*UPN;
        float ang = (float)spos * tab.inv[dd];
        float c, sn; sincosf(ang, &sn, &c);
        #pragma unroll
        for (int pp = 0; pp < 2; pp++) {
            int p = tid + pp*256;            // 0..511
            int hh = p >> 5;
            int i1 = hh*DHH + dd, i2 = i1 + 32;
            float q1 = __bfloat162float(um[i1]);
            float q2 = __bfloat162float(um[i2]);
            size_t qo = (((size_t)(b*NHH + hh))*SS + spos)*DHH;
            g_Q[qo + dd]      = q1*c - q2*sn;
            g_Q[qo + 32 + dd] = q2*c + q1*sn;
            float k1 = __bfloat162float(um[QKVD + i1]) + (i1 < 256 ? kadds[u][i1] : 0.f);
            float k2 = __bfloat162float(um[QKVD + i2]) + (i2 < 256 ? kadds[u][i2] : 0.f);
            size_t ko = (((size_t)(b*NHH + hh))*KVL + RG + spos)*DHH;
            g_K[ko + dd]      = k1*c - k2*sn;
            g_K[ko + 32 + dd] = k2*c + k1*sn;
        }
        #pragma unroll
        for (int pp = 0; pp < 4; pp++) {
            int p = tid + pp*256;            // 0..1023
            int hh = p >> 6;
            float vv = __bfloat162float(um[2*QKVD + p]) + (p < 256 ? vadds[u][p] : 0.f);
            g_V[(((size_t)(b*NHH + hh))*KVS + RG + spos)*DHH + (p & 63)] = vv;
        }
    }
}

// register tokens K/V fill + V pad-row zeroing
__global__ void regfill_kernel(const float* __restrict__ reg_k, const float* __restrict__ reg_v)
{
    int bh = blockIdx.x, hh = bh & 15;
    int j = threadIdx.x >> 6, d = threadIdx.x & 63;
    g_K[((size_t)bh*KVL + j)*DHH + d] = reg_k[((size_t)j*NHH + hh)*DHH + d];
    g_V[((size_t)bh*KVS + j)*DHH + d] = reg_v[((size_t)j*NHH + hh)*DHH + d];
    for (int idx = threadIdx.x; idx < (KVS - KVL)*DHH; idx += blockDim.x)
        g_V[((size_t)bh*KVS + KVL)*DHH + idx] = 0.f;
}

// =======================================================================
// Kernel 4: FLASH attention (fused QK^T + online softmax + PV), tf32
// =======================================================================
#define KSP 68
#define VSP 72
#define FLASH_SMEM ((128*KSP + 128*VSP)*4)

__global__ void __launch_bounds__(256) flash_kernel(const float* __restrict__ attn_mask)
{
    extern __shared__ float sf[];
    float* Ks = sf;
    float* Vs = sf + 128*KSP;
    const int tid = threadIdx.x, lane = tid & 31, w = tid >> 5;
    const int g = lane >> 2, t = lane & 3;
    const int bh = blockIdx.y, b = bh >> 4, hh = bh & 15;
    const int bm = blockIdx.x * 128;
    const float* Qb = g_Q + (size_t)bh*SS*DHH;
    const float* Kb = g_K + (size_t)bh*KVL*DHH;
    const float* Vb = g_V + (size_t)bh*KVS*DHH;

    #pragma unroll
    for (int j = 0; j < 8; j++) {
        int idx = tid + j*256;
        int r = idx >> 4, c4 = idx & 15;
        float4 q = *(const float4*)(Qb + (size_t)(bm + r)*DHH + c4*4);
        float* p = Ks + r*KSP + c4*4;
        p[0]=cvtf(q.x); p[1]=cvtf(q.y); p[2]=cvtf(q.z); p[3]=cvtf(q.w);
    }
    __syncthreads();
    unsigned aQ[8][4];
    #pragma unroll
    for (int k = 0; k < 8; k++) {
        const float* p0 = Ks + (w*16 + g)*KSP + k*8;
        const float* p1 = p0 + 8*KSP;
        aQ[k][0] = ldsu(p0 + t);
        aQ[k][1] = ldsu(p1 + t);
        aQ[k][2] = ldsu(p0 + t + 4);
        aQ[k][3] = ldsu(p1 + t + 4);
    }
    __syncthreads();

    float accO[8][4];
    #pragma unroll
    for (int vn = 0; vn < 8; vn++)
        #pragma unroll
        for (int e = 0; e < 4; e++) accO[vn][e] = 0.f;
    float mrow0 = -1e30f, mrow1 = -1e30f, lrow0 = 0.f, lrow1 = 0.f;

    const int gi0 = bm + w*16 + g, gi1 = gi0 + 8;
    const float* am0 = attn_mask + ((size_t)b*SS + gi0)*SS;
    const float* am1 = attn_mask + ((size_t)b*SS + gi1)*SS;
    const bool iafh = (hh < NIAFH);

    for (int j0 = 0; j0 < KVL; j0 += 128) {
        #pragma unroll
        for (int j = 0; j < 8; j++) {
            int idx = tid + j*256;
            int r = idx >> 4, c4 = idx & 15;
            bool ok = (j0 + r) < KVL;
            float4 kv = ok ? *(const float4*)(Kb + (size_t)(j0 + r)*DHH + c4*4)
                           : make_float4(0.f,0.f,0.f,0.f);
            float* pk = Ks + r*KSP + c4*4;
            pk[0]=cvtf(kv.x); pk[1]=cvtf(kv.y); pk[2]=cvtf(kv.z); pk[3]=cvtf(kv.w);
            float4 vv = ok ? *(const float4*)(Vb + (size_t)(j0 + r)*DHH + c4*4)
                           : make_float4(0.f,0.f,0.f,0.f);
            float* pv = Vs + r*VSP + c4*4;
            pv[0]=cvtf(vv.x); pv[1]=cvtf(vv.y); pv[2]=cvtf(vv.z); pv[3]=cvtf(vv.w);
        }
        __syncthreads();

        float s[16][4];
        #pragma unroll
        for (int nt = 0; nt < 16; nt++)
            #pragma unroll
            for (int e = 0; e < 4; e++) s[nt][e] = 0.f;
        #pragma unroll
        for (int ks = 0; ks < 8; ks++) {
            #pragma unroll
            for (int nt = 0; nt < 16; nt++) {
                unsigned bb[2];
                const float* pn = Ks + (nt*8 + g)*KSP + ks*8;
                bb[0] = ldsu(pn + t);
                bb[1] = ldsu(pn + t + 4);
                mma8(s[nt], aQ[ks], bb);
            }
        }

        float tmax0 = -1e30f, tmax1 = -1e30f;
        #pragma unroll
        for (int nt = 0; nt < 16; nt++) {
            int colbase = j0 + nt*8;
            if (colbase >= KVL) {
                s[nt][0] = s[nt][1] = s[nt][2] = s[nt][3] = -1e30f;
            } else if (colbase < RG) {
                s[nt][0] *= 0.125f; s[nt][1] *= 0.125f;
                s[nt][2] *= 0.125f; s[nt][3] *= 0.125f;
            } else {
                int js = colbase + 2*t - RG;
                float2 a0 = *(const float2*)(am0 + js);
                float2 a1 = *(const float2*)(am1 + js);
                float mk00 = a0.x, mk01 = a0.y, mk10 = a1.x, mk11 = a1.y;
                if (iafh) {
                    if (js     >= gi0) mk00 += NEGV;
                    if (js + 1 >= gi0) mk01 += NEGV;
                    if (js     >= gi1) mk10 += NEGV;
                    if (js + 1 >= gi1) mk11 += NEGV;
                }
                s[nt][0] = s[nt][0]*0.125f + mk00;
                s[nt][1] = s[nt][1]*0.125f + mk01;
                s[nt][2] = s[nt][2]*0.125f + mk10;
                s[nt][3] = s[nt][3]*0.125f + mk11;
            }
            tmax0 = fmaxf(tmax0, fmaxf(s[nt][0], s[nt][1]));
            tmax1 = fmaxf(tmax1, fmaxf(s[nt][2], s[nt][3]));
        }
        tmax0 = fmaxf(tmax0, __shfl_xor_sync(0xffffffffu, tmax0, 1));
        tmax0 = fmaxf(tmax0, __shfl_xor_sync(0xffffffffu, tmax0, 2));
        tmax1 = fmaxf(tmax1, __shfl_xor_sync(0xffffffffu, tmax1, 1));
        tmax1 = fmaxf(tmax1, __shfl_xor_sync(0xffffffffu, tmax1, 2));

        float newm0 = fmaxf(mrow0, tmax0);
        float newm1 = fmaxf(mrow1, tmax1);
        float sc0 = __expf(mrow0 - newm0);
        float sc1 = __expf(mrow1 - newm1);
        float rs0 = 0.f, rs1 = 0.f;
        #pragma unroll
        for (int nt = 0; nt < 16; nt++) {
            float p0 = __expf(s[nt][0] - newm0);
            float p1 = __expf(s[nt][1] - newm0);
            float p2 = __expf(s[nt][2] - newm1);
            float p3 = __expf(s[nt][3] - newm1);
            s[nt][0] = p0; s[nt][1] = p1; s[nt][2] = p2; s[nt][3] = p3;
            rs0 += p0 + p1; rs1 += p2 + p3;
        }
        rs0 += __shfl_xor_sync(0xffffffffu, rs0, 1);
        rs0 += __shfl_xor_sync(0xffffffffu, rs0, 2);
        rs1 += __shfl_xor_sync(0xffffffffu, rs1, 1);
        rs1 += __shfl_xor_sync(0xffffffffu, rs1, 2);
        lrow0 = lrow0*sc0 + rs0;
        lrow1 = lrow1*sc1 + rs1;
        mrow0 = newm0; mrow1 = newm1;
        #pragma unroll
        for (int vn = 0; vn < 8; vn++) {
            accO[vn][0] *= sc0; accO[vn][1] *= sc0;
            accO[vn][2] *= sc1; accO[vn][3] *= sc1;
        }

        const int qb = lane & ~3;
        const int s0l = qb + (t >> 1), s1l = s0l + 2;
        const bool odd = (t & 1);
        #pragma unroll
        for (int ks = 0; ks < 16; ks++) {
            float x0 = __shfl_sync(0xffffffffu, s[ks][0], s0l);
            float x1 = __shfl_sync(0xffffffffu, s[ks][1], s0l);
            float y0 = __shfl_sync(0xffffffffu, s[ks][2], s0l);
            float y1 = __shfl_sync(0xffffffffu, s[ks][3], s0l);
            float x0b = __shfl_sync(0xffffffffu, s[ks][0], s1l);
            float x1b = __shfl_sync(0xffffffffu, s[ks][1], s1l);
            float y0b = __shfl_sync(0xffffffffu, s[ks][2], s1l);
            float y1b = __shfl_sync(0xffffffffu, s[ks][3], s1l);
            unsigned aP[4];
            aP[0] = cvt_tf32(odd ? x1  : x0);
            aP[1] = cvt_tf32(odd ? y1  : y0);
            aP[2] = cvt_tf32(odd ? x1b : x0b);
            aP[3] = cvt_tf32(odd ? y1b : y0b);
            #pragma unroll
            for (int vn = 0; vn < 8; vn++) {
                unsigned bb[2];
                bb[0] = ldsu(Vs + (ks*8 + t)*VSP + vn*8 + g);
                bb[1] = ldsu(Vs + (ks*8 + t + 4)*VSP + vn*8 + g);
                mma8(accO[vn], aP, bb);
            }
        }
        __syncthreads();
    }

    float inv0 = 1.f / lrow0, inv1 = 1.f / lrow1;
    int row0 = b*SS + gi0, row1 = b*SS + gi1;
    #pragma unroll
    for (int vn = 0; vn < 8; vn++) {
        int n = vn*8 + 2*t;
        *(__nv_bfloat162*)(g_down_b + (size_t)row0*DWK + ZD + hh*DHH + n) =
            __floats2bfloat162_rn(accO[vn][0]*inv0, accO[vn][1]*inv0);
        *(__nv_bfloat162*)(g_down_b + (size_t)row1*DWK + ZD + hh*DHH + n) =
            __floats2bfloat162_rn(accO[vn][2]*inv1, accO[vn][3]*inv1);
    }
}

// =======================================================================
// Kernel 5: mlp = silu(gate)*val into g_down_b (bf16x2)
// =======================================================================
__global__ void __launch_bounds__(256) mlp_kernel()
{
    size_t idx = (size_t)blockIdx.x*256 + threadIdx.x;   // over NTOK*MLPD/2
    int m = (int)(idx >> 11);
    int jj = (int)(idx & 2047);
    const __nv_bfloat162* gp = (const __nv_bfloat162*)(g_u_b + (size_t)m*UPN + 3*QKVD) + jj;
    const __nv_bfloat162* vp = (const __nv_bfloat162*)(g_u_b + (size_t)m*UPN + 3*QKVD + MLPD) + jj;
    float2 gv = __bfloat1622float2(*gp);
    float2 vv = __bfloat1622float2(*vp);
    float r0 = gv.x / (1.f + __expf(-gv.x)) * vv.x;
    float r1 = gv.y / (1.f + __expf(-gv.y)) * vv.y;
    *((__nv_bfloat162*)(g_down_b + (size_t)m*DWK + ZD + QKVD) + jj) =
        __floats2bfloat162_rn(r0, r1);
}

// =======================================================================
// launch
// =======================================================================
extern "C" void kernel_launch(void* const* d_in, const int* in_sizes, int n_in,
                              void* d_out, int out_size)
{
    const float* hs          = (const float*)d_in[0];
    const unsigned char* msk = (const unsigned char*)d_in[1];
    const float* noise       = (const float*)d_in[2];
    const float* next_noise  = (const float*)d_in[3];
    const float* attn_mask   = (const float*)d_in[4];
    const float* ln_w        = (const float*)d_in[5];
    const float* ln_b        = (const float*)d_in[6];
    const float* alpha       = (const float*)d_in[7];
    const float* iaf_wx      = (const float*)d_in[8];
    const float* iaf_wn      = (const float*)d_in[9];
    const float* iaf_w2      = (const float*)d_in[10];
    const float* up_w        = (const float*)d_in[11];
    const float* iaf_up_w    = (const float*)d_in[12];
    const float* down_w      = (const float*)d_in[13];
    const float* reg_k       = (const float*)d_in[14];
    const float* reg_v       = (const float*)d_in[15];
    float* out = (float*)d_out;

    __nv_bfloat16 *p_xz, *p_u, *p_down, *p_upw, *p_dnw;
    cudaGetSymbolAddress((void**)&p_xz, g_xz_b);
    cudaGetSymbolAddress((void**)&p_u, g_u_b);
    cudaGetSymbolAddress((void**)&p_down, g_down_b);
    cudaGetSymbolAddress((void**)&p_upw, g_upw_b);
    cudaGetSymbolAddress((void**)&p_dnw, g_dnw_b);

    const int GEMM_SMEM = (2*128 + 2*256)*APITCH*2;   // 61440
    (void)cudaFuncSetAttribute(bf16_gemm_nt<0>, cudaFuncAttributeMaxDynamicSharedMemorySize, GEMM_SMEM);
    (void)cudaFuncSetAttribute(bf16_gemm_nt<1>, cudaFuncAttributeMaxDynamicSharedMemorySize, GEMM_SMEM);
    (void)cudaFuncSetAttribute(flash_kernel, cudaFuncAttributeMaxDynamicSharedMemorySize, FLASH_SMEM);

    RopeTab rt;
    for (int d = 0; d < 32; d++) {
        float pw = powf(10000.f, (float)(2*d) / 64.f);
        rt.inv[d] = 1.f / pw;
    }

    detect_mask_kernel<<<1, 32>>>(msk);

    // weight conversion (fp32 -> bf16)
    convert_bf16_kernel<<<(UPN*UPK/2 + 255)/256, 256>>>(up_w, p_upw, UPN*UPK/2);
    convert_bf16_kernel<<<(DD*DWK/2 + 255)/256, 256>>>(down_w, p_dnw, DD*DWK/2);

    token_kernel<<<NTOK/8, 128>>>(hs, msk, noise, ln_w, ln_b, iaf_wx, iaf_wn, iaf_w2, out);

    bf16_gemm_nt<0><<<dim3(UPN/256, NTOK/128), 256, GEMM_SMEM>>>(
        p_xz, p_upw, p_u, NTOK, UPN, UPK, nullptr, nullptr);

    prep_qkv<<<NTOK/8, 256>>>(next_noise, iaf_up_w, rt);
    regfill_kernel<<<BB*NHH, 512>>>(reg_k, reg_v);

    flash_kernel<<<dim3(SS/128, BB*NHH), 256, FLASH_SMEM>>>(attn_mask);

    mlp_kernel<<<(NTOK*MLPD/2)/256, 256>>>();

    bf16_gemm_nt<1><<<dim3(DD/256, NTOK/128), 256, GEMM_SMEM>>>(
        p_down, p_dnw, out, NTOK, DD, DWK, hs, alpha);
}

// round 13
// speedup vs baseline: 3.4887x; 1.0886x over previous
#include <cuda_runtime.h>
#include <cuda_bf16.h>
#include <math.h>

// ---------------- problem constants ----------------
#define BB 2
#define SS 2048
#define DD 1024
#define NHH 16
#define DHH 64
#define NIAFH 4
#define QKVD 1024
#define MLPD 4096
#define ZD 32
#define HIAFD 128
#define HIAFP 256              // padded hdn width for GEMM (N%256==0)
#define XAK 3072               // split-GEMM K: [x_hi | x_hi | x_lo]
#define RG 8
#define KVL (SS + RG)          // 2056
#define KVS 2080               // padded V stride
#define UPN (QKVD + 2*QKVD + 2*MLPD)   // 11264
#define UPK (DD + ZD)          // 1056
#define DWK (ZD + QKVD + MLPD) // 5152
#define NTOK (BB*SS)           // 4096

#define ZSCALE 0.04419417382415922f    // sqrt(1/(32*16))
#define SPSHIFT 0.5413248546129181f    // log(e-1)
#define NEGV -1000000000.0f

// output layout: h_out | z | mu | sigma
#define OFF_Z  (NTOK*DD)
#define OFF_MU (OFF_Z + NTOK*ZD)
#define OFF_SG (OFF_MU + NTOK*ZD)

// ---------------- scratch ----------------
__device__ __nv_bfloat16 g_xz_b[(size_t)NTOK*UPK];     // [x | z] bf16
__device__ __nv_bfloat16 g_u_b[(size_t)NTOK*UPN];      // up-proj out bf16
__device__ __nv_bfloat16 g_down_b[(size_t)NTOK*DWK];   // [z|attn|mlp] bf16
__device__ __nv_bfloat16 g_upw_b[(size_t)UPN*UPK];     // bf16 up weights
__device__ __nv_bfloat16 g_dnw_b[(size_t)DD*DWK];      // bf16 down weights
__device__ __nv_bfloat16 g_xa[(size_t)NTOK*XAK];       // [x_hi | x_hi | x_lo]
__device__ __nv_bfloat16 g_wxs[(size_t)HIAFP*XAK];     // [w_hi | w_lo | w_hi] (pad rows 0)
__device__ float        g_hdnp[(size_t)NTOK*HIAFP];    // hdn pre-activation fp32
__device__ float g_Q[(size_t)BB*NHH*SS*DHH];
__device__ float g_K[(size_t)BB*NHH*KVL*DHH];
__device__ float g_V[(size_t)BB*NHH*KVS*DHH];
__device__ int   g_mask_mode;

struct RopeTab { float inv[32]; };

// ---------------- mma helpers ----------------
__device__ __forceinline__ unsigned cvt_tf32(float x) {
    unsigned r;
    asm("cvt.rna.tf32.f32 %0, %1;" : "=r"(r) : "f"(x));
    return r;
}
__device__ __forceinline__ float cvtf(float x) { return __uint_as_float(cvt_tf32(x)); }

__device__ __forceinline__ void mma8(float* d, const unsigned* a, const unsigned* b) {
    asm volatile(
        "mma.sync.aligned.m16n8k8.row.col.f32.tf32.tf32.f32 "
        "{%0,%1,%2,%3}, {%4,%5,%6,%7}, {%8,%9}, {%0,%1,%2,%3};"
        : "+f"(d[0]), "+f"(d[1]), "+f"(d[2]), "+f"(d[3])
        : "r"(a[0]), "r"(a[1]), "r"(a[2]), "r"(a[3]), "r"(b[0]), "r"(b[1]));
}
__device__ __forceinline__ void mma16bf(float* d, const unsigned* a, const unsigned* b) {
    asm volatile(
        "mma.sync.aligned.m16n8k16.row.col.f32.bf16.bf16.f32 "
        "{%0,%1,%2,%3}, {%4,%5,%6,%7}, {%8,%9}, {%0,%1,%2,%3};"
        : "+f"(d[0]), "+f"(d[1]), "+f"(d[2]), "+f"(d[3])
        : "r"(a[0]), "r"(a[1]), "r"(a[2]), "r"(a[3]), "r"(b[0]), "r"(b[1]));
}
__device__ __forceinline__ unsigned ldsu(const float* p) { return __float_as_uint(*p); }
__device__ __forceinline__ unsigned smem_u32(const void* p) {
    return (unsigned)__cvta_generic_to_shared(p);
}

// =======================================================================
// Kernel 0: classify the storage dtype of the bool `mask` input.
// =======================================================================
__global__ void detect_mask_kernel(const unsigned char* __restrict__ p)
{
    if (threadIdx.x != 0 || blockIdx.x != 0) return;
    const unsigned int* w = (const unsigned int*)p;
    bool allf = true, anyf = false, i32ok = true;
    for (int i = 0; i < 1024; i++) {
        unsigned int v = w[i];
        if (v == 0x3F800000u) anyf = true;
        else if (v != 0u) allf = false;
        if ((v & 0xFFFFFF00u) != 0u) i32ok = false;
    }
    g_mask_mode = (allf && anyf) ? 2 : (i32ok ? 1 : 0);
}

__device__ __forceinline__ float read_mask(const unsigned char* p, int m, int mode)
{
    if (mode == 1) return ((const int*)p)[m] != 0 ? 1.f : 0.f;
    if (mode == 2) return ((const float*)p)[m] != 0.f ? 1.f : 0.f;
    return p[m] != 0 ? 1.f : 0.f;
}

// =======================================================================
// Kernel 0b: fp32 -> bf16 conversion
// =======================================================================
__global__ void convert_bf16_kernel(const float* __restrict__ src,
                                    __nv_bfloat16* __restrict__ dst, int n2)
{
    int i = blockIdx.x*256 + threadIdx.x;
    if (i < n2) {
        float2 v = ((const float2*)src)[i];
        ((__nv_bfloat162*)dst)[i] = __floats2bfloat162_rn(v.x, v.y);
    }
}

// iaf_wx split: g_wxs[j][0..1023]=w_hi, [1024..2047]=w_lo, [2048..3071]=w_hi
// rows j>=128 zero.
__global__ void convert_wxs_kernel(const float* __restrict__ wx)
{
    int idx = blockIdx.x*256 + threadIdx.x;      // over HIAFP*DD
    if (idx >= HIAFP*DD) return;
    int j = idx >> 10, d = idx & 1023;
    __nv_bfloat16 hi, lo;
    if (j < HIAFD) {
        float w = wx[(size_t)j*DD + d];
        hi = __float2bfloat16(w);
        lo = __float2bfloat16(w - __bfloat162float(hi));
    } else {
        hi = __float2bfloat16(0.f);
        lo = __float2bfloat16(0.f);
    }
    __nv_bfloat16* row = g_wxs + (size_t)j*XAK;
    row[d] = hi;
    row[1024 + d] = lo;
    row[2048 + d] = hi;
}

// =======================================================================
// Kernel 1a: LayerNorm per token -> bf16 x (+ split hi/lo into g_xa)
// =======================================================================
__global__ void __launch_bounds__(128) ln_kernel(
    const float* __restrict__ hs,
    const float* __restrict__ ln_w, const float* __restrict__ ln_b)
{
    __shared__ float redS[4], redQ[4], stat[2];
    const int tid = threadIdx.x, lane = tid & 31, wid = tid >> 5;
    const int m = blockIdx.x;
    const float* hp = hs + (size_t)m*DD;

    float4 xv[2];
    float s = 0.f, q = 0.f;
    #pragma unroll
    for (int k = 0; k < 2; k++) {
        xv[k] = *(const float4*)(hp + tid*4 + k*512);
        s += xv[k].x + xv[k].y + xv[k].z + xv[k].w;
        q += xv[k].x*xv[k].x + xv[k].y*xv[k].y + xv[k].z*xv[k].z + xv[k].w*xv[k].w;
    }
    #pragma unroll
    for (int o = 16; o; o >>= 1) {
        s += __shfl_down_sync(0xffffffffu, s, o);
        q += __shfl_down_sync(0xffffffffu, q, o);
    }
    if (lane == 0) { redS[wid] = s; redQ[wid] = q; }
    __syncthreads();
    if (tid == 0) {
        float S1 = redS[0]+redS[1]+redS[2]+redS[3];
        float Q1 = redQ[0]+redQ[1]+redQ[2]+redQ[3];
        float mean = S1 / (float)DD;
        float var  = Q1 / (float)DD - mean*mean;
        stat[0] = mean;
        stat[1] = rsqrtf(var + 1e-5f);
    }
    __syncthreads();
    float mean = stat[0], rstd = stat[1];
    __nv_bfloat16* xzr = g_xz_b + (size_t)m*UPK;
    __nv_bfloat16* xar = g_xa + (size_t)m*XAK;
    #pragma unroll
    for (int k = 0; k < 2; k++) {
        int d = tid*4 + k*512;
        float4 wv = *(const float4*)(ln_w + d);
        float4 bv = *(const float4*)(ln_b + d);
        float xf[4];
        xf[0] = (xv[k].x - mean)*rstd*wv.x + bv.x;
        xf[1] = (xv[k].y - mean)*rstd*wv.y + bv.y;
        xf[2] = (xv[k].z - mean)*rstd*wv.z + bv.z;
        xf[3] = (xv[k].w - mean)*rstd*wv.w + bv.w;
        #pragma unroll
        for (int e = 0; e < 4; e++) {
            __nv_bfloat16 hi = __float2bfloat16(xf[e]);
            __nv_bfloat16 lo = __float2bfloat16(xf[e] - __bfloat162float(hi));
            xzr[d + e] = hi;
            xar[d + e] = hi;
            xar[1024 + d + e] = hi;
            xar[2048 + d + e] = lo;
        }
    }
}

// =======================================================================
// Kernel 1b: z/mu/sigma from fp32 hdn-pre + noise terms (8 tokens/block)
// =======================================================================
__global__ void __launch_bounds__(128) z_kernel(
    const unsigned char* __restrict__ mask, const float* __restrict__ noise,
    const float* __restrict__ iaf_wn, const float* __restrict__ iaf_w2,
    float* __restrict__ out)
{
    __shared__ float ns[8][ZD];
    __shared__ float hdn[8][HIAFD];
    __shared__ float zps[8][2*ZD];
    __shared__ float fmv[8];
    const int tid = threadIdx.x;
    const int m0 = blockIdx.x * 8;
    const int mmode = g_mask_mode;

    {
        int t = tid >> 5, i = tid & 31;
        float fm = read_mask(mask, m0 + t, mmode);
        ns[t][i] = noise[(size_t)(m0 + t)*ZD + i] * fm;
        ns[t + 4][i] = noise[(size_t)(m0 + t + 4)*ZD + i] *
                       read_mask(mask, m0 + t + 4, mmode);
        if (i == 0) {
            fmv[t] = fm;
            fmv[t + 4] = read_mask(mask, m0 + t + 4, mmode);
        }
    }
    __syncthreads();

    {
        int j = tid;
        float acc[8];
        #pragma unroll
        for (int t = 0; t < 8; t++)
            acc[t] = g_hdnp[(size_t)(m0 + t)*HIAFP + j];
        int dm = j % 31;                 // M1[j][i] = (i <= j%31)
        const float* wn = iaf_wn + (size_t)j*ZD;
        for (int i = 0; i <= dm; i++) {
            float w = wn[i];
            #pragma unroll
            for (int t = 0; t < 8; t++) acc[t] += ns[t][i]*w;
        }
        #pragma unroll
        for (int t = 0; t < 8; t++) {
            float v = acc[t];
            hdn[t][j] = v / (1.f + __expf(-v));
        }
    }
    __syncthreads();

    if (tid < 64) {
        int o = tid, lim = o & 31;       // M2[o][j] = (j%31 < o%32)
        float acc[8];
        #pragma unroll
        for (int t = 0; t < 8; t++) acc[t] = 0.f;
        const float* w2 = iaf_w2 + (size_t)o*HIAFD;
        for (int j = 0; j < HIAFD; j++) {
            if ((j % 31) < lim) {
                float w = w2[j];
                #pragma unroll
                for (int t = 0; t < 8; t++) acc[t] += hdn[t][j]*w;
            }
        }
        #pragma unroll
        for (int t = 0; t < 8; t++) zps[t][o] = fmv[t]*ZSCALE*acc[t];
    }
    __syncthreads();

    for (int idx = tid; idx < 8*ZD; idx += 128) {
        int t = idx >> 5, i = idx & 31;
        int m = m0 + t;
        float mu = zps[t][i];
        float ls = zps[t][ZD + i] + SPSHIFT;
        float sg = (ls > 20.f) ? ls : log1pf(expf(ls));
        float z  = mu + sg*ns[t][i];
        g_xz_b[(size_t)m*UPK + DD + i] = __float2bfloat16(z);
        g_down_b[(size_t)m*DWK + i]    = __float2bfloat16(z);
        out[OFF_Z  + (size_t)m*ZD + i] = z;
        out[OFF_MU + (size_t)m*ZD + i] = mu;
        out[OFF_SG + (size_t)m*ZD + i] = sg;
    }
}

// =======================================================================
// Kernel 2: BF16 GEMM 128x256x32, cp.async double-buffered, m16n8k16.
//   EPI=0: C bf16;  EPI=1: C fp32 = addsrc+alpha*acc;  EPI=2: C fp32 plain
// =======================================================================
#define APITCH 40

__device__ __forceinline__ void bgemm_prefetch(
    const __nv_bfloat16* __restrict__ A, const __nv_bfloat16* __restrict__ B,
    __nv_bfloat16* As, __nv_bfloat16* Bs, int bm, int bn, int lda, int ldb, int k0, int tid)
{
    #pragma unroll
    for (int j = 0; j < 2; j++) {
        int idx = tid + j*256, r = idx >> 2, c = idx & 3;
        unsigned d = smem_u32(As + r*APITCH + c*8);
        asm volatile("cp.async.ca.shared.global [%0], [%1], 16;"
                     :: "r"(d), "l"(A + (size_t)(bm + r)*lda + k0 + c*8));
    }
    #pragma unroll
    for (int j = 0; j < 4; j++) {
        int idx = tid + j*256, r = idx >> 2, c = idx & 3;
        unsigned d = smem_u32(Bs + r*APITCH + c*8);
        asm volatile("cp.async.ca.shared.global [%0], [%1], 16;"
                     :: "r"(d), "l"(B + (size_t)(bn + r)*ldb + k0 + c*8));
    }
}

template<int EPI>
__global__ void __launch_bounds__(256) bf16_gemm_nt(
    const __nv_bfloat16* __restrict__ A, const __nv_bfloat16* __restrict__ Bw, void* Cp,
    int M, int N, int K, int lda, int ldb,
    const float* __restrict__ addsrc, const float* __restrict__ alphap)
{
    extern __shared__ __nv_bfloat16 smb[];
    __nv_bfloat16* Asb[2] = { smb, smb + 128*APITCH };
    __nv_bfloat16* Bsb[2] = { smb + 2*128*APITCH, smb + 2*128*APITCH + 256*APITCH };
    const int tid = threadIdx.x;
    const int lane = tid & 31, wid = tid >> 5;
    const int g = lane >> 2, t = lane & 3;
    const int wm = (wid >> 2) * 64, wn = (wid & 3) * 64;
    const int bm = blockIdx.y * 128, bn = blockIdx.x * 256;

    float acc[4][8][4];
    #pragma unroll
    for (int mi = 0; mi < 4; mi++)
        #pragma unroll
        for (int ni = 0; ni < 8; ni++)
            #pragma unroll
            for (int e = 0; e < 4; e++) acc[mi][ni][e] = 0.f;

    const int KT = K / 32;
    bgemm_prefetch(A, Bw, Asb[0], Bsb[0], bm, bn, lda, ldb, 0, tid);
    asm volatile("cp.async.commit_group;");

    for (int kt = 0; kt < KT; kt++) {
        const int buf = kt & 1;
        if (kt + 1 < KT) {
            bgemm_prefetch(A, Bw, Asb[buf^1], Bsb[buf^1], bm, bn, lda, ldb, (kt+1)*32, tid);
            asm volatile("cp.async.commit_group;");
            asm volatile("cp.async.wait_group 1;");
        } else {
            asm volatile("cp.async.wait_group 0;");
        }
        __syncthreads();
        const __nv_bfloat16* As = Asb[buf];
        const __nv_bfloat16* Bs = Bsb[buf];
        #pragma unroll
        for (int ks = 0; ks < 32; ks += 16) {
            unsigned a[4][4], b[8][2];
            #pragma unroll
            for (int mi = 0; mi < 4; mi++) {
                const __nv_bfloat16* p0 = As + (wm + mi*16 + g)*APITCH + ks + 2*t;
                a[mi][0] = *(const unsigned*)(p0);
                a[mi][1] = *(const unsigned*)(p0 + 8*APITCH);
                a[mi][2] = *(const unsigned*)(p0 + 8);
                a[mi][3] = *(const unsigned*)(p0 + 8*APITCH + 8);
            }
            #pragma unroll
            for (int ni = 0; ni < 8; ni++) {
                const __nv_bfloat16* pn = Bs + (wn + ni*8 + g)*APITCH + ks + 2*t;
                b[ni][0] = *(const unsigned*)(pn);
                b[ni][1] = *(const unsigned*)(pn + 8);
            }
            #pragma unroll
            for (int mi = 0; mi < 4; mi++)
                #pragma unroll
                for (int ni = 0; ni < 8; ni++)
                    mma16bf(acc[mi][ni], a[mi], b[ni]);
        }
        __syncthreads();
    }

    float alpha = (EPI == 1) ? *alphap : 0.f;
    #pragma unroll
    for (int mi = 0; mi < 4; mi++) {
        int r0 = bm + wm + mi*16 + g;
        #pragma unroll
        for (int ni = 0; ni < 8; ni++) {
            int c0 = bn + wn + ni*8 + 2*t;
            #pragma unroll
            for (int h = 0; h < 2; h++) {
                int row = r0 + 8*h;
                size_t o = (size_t)row*N + c0;
                float v0 = acc[mi][ni][2*h], v1 = acc[mi][ni][2*h + 1];
                if (EPI == 1) {
                    float* C = (float*)Cp;
                    C[o]   = addsrc[o]   + alpha*v0;
                    C[o+1] = addsrc[o+1] + alpha*v1;
                } else if (EPI == 2) {
                    float* C = (float*)Cp;
                    C[o]   = v0;
                    C[o+1] = v1;
                } else {
                    __nv_bfloat16* C = (__nv_bfloat16*)Cp;
                    *(__nv_bfloat162*)(C + o) = __floats2bfloat162_rn(v0, v1);
                }
            }
        }
    }
}

// =======================================================================
// Kernel 3: QKV prep — 8 tokens/block, bf16 u reads, RoPE, fp32 QKV out
// =======================================================================
__global__ void __launch_bounds__(256) prep_qkv(
    const float* __restrict__ next_noise, const float* __restrict__ iaf_up_w, RopeTab tab)
{
    __shared__ float nn[8][ZD];
    __shared__ float kadds[8][256], vadds[8][256];
    const int tid = threadIdx.x;
    const int m0 = blockIdx.x * 8;

    {
        int t8 = tid >> 5, i = tid & 31;
        nn[t8][i] = next_noise[(size_t)(m0 + t8)*ZD + i];
    }
    __syncthreads();
    {
        const float* wk = iaf_up_w + (size_t)tid*ZD;
        const float* wv = iaf_up_w + (size_t)(QKVD + tid)*ZD;
        float ka[8], va[8];
        #pragma unroll
        for (int u = 0; u < 8; u++) { ka[u] = 0.f; va[u] = 0.f; }
        #pragma unroll 4
        for (int i = 0; i < ZD; i++) {
            float wki = wk[i], wvi = wv[i];
            #pragma unroll
            for (int u = 0; u < 8; u++) {
                ka[u] += nn[u][i]*wki;
                va[u] += nn[u][i]*wvi;
            }
        }
        #pragma unroll
        for (int u = 0; u < 8; u++) { kadds[u][tid] = ka[u]; vadds[u][tid] = va[u]; }
    }
    __syncthreads();

    const int dd = tid & 31;
    for (int u = 0; u < 8; u++) {
        int m = m0 + u;
        int b = m >> 11, spos = m & 2047;
        const __nv_bfloat16* um = g_u_b + (size_t)m*UPN;
        float ang = (float)spos * tab.inv[dd];
        float c, sn; sincosf(ang, &sn, &c);
        #pragma unroll
        for (int pp = 0; pp < 2; pp++) {
            int p = tid + pp*256;            // 0..511
            int hh = p >> 5;
            int i1 = hh*DHH + dd, i2 = i1 + 32;
            float q1 = __bfloat162float(um[i1]);
            float q2 = __bfloat162float(um[i2]);
            size_t qo = (((size_t)(b*NHH + hh))*SS + spos)*DHH;
            g_Q[qo + dd]      = q1*c - q2*sn;
            g_Q[qo + 32 + dd] = q2*c + q1*sn;
            float k1 = __bfloat162float(um[QKVD + i1]) + (i1 < 256 ? kadds[u][i1] : 0.f);
            float k2 = __bfloat162float(um[QKVD + i2]) + (i2 < 256 ? kadds[u][i2] : 0.f);
            size_t ko = (((size_t)(b*NHH + hh))*KVL + RG + spos)*DHH;
            g_K[ko + dd]      = k1*c - k2*sn;
            g_K[ko + 32 + dd] = k2*c + k1*sn;
        }
        #pragma unroll
        for (int pp = 0; pp < 4; pp++) {
            int p = tid + pp*256;            // 0..1023
            int hh = p >> 6;
            float vv = __bfloat162float(um[2*QKVD + p]) + (p < 256 ? vadds[u][p] : 0.f);
            g_V[(((size_t)(b*NHH + hh))*KVS + RG + spos)*DHH + (p & 63)] = vv;
        }
    }
}

// register tokens K/V fill + V pad-row zeroing
__global__ void regfill_kernel(const float* __restrict__ reg_k, const float* __restrict__ reg_v)
{
    int bh = blockIdx.x, hh = bh & 15;
    int j = threadIdx.x >> 6, d = threadIdx.x & 63;
    g_K[((size_t)bh*KVL + j)*DHH + d] = reg_k[((size_t)j*NHH + hh)*DHH + d];
    g_V[((size_t)bh*KVS + j)*DHH + d] = reg_v[((size_t)j*NHH + hh)*DHH + d];
    for (int idx = threadIdx.x; idx < (KVS - KVL)*DHH; idx += blockDim.x)
        g_V[((size_t)bh*KVS + KVL)*DHH + idx] = 0.f;
}

// =======================================================================
// Kernel 4: FLASH attention (fused QK^T + online softmax + PV), tf32
// =======================================================================
#define KSP 68
#define VSP 72
#define FLASH_SMEM ((128*KSP + 128*VSP)*4)

__global__ void __launch_bounds__(256) flash_kernel(const float* __restrict__ attn_mask)
{
    extern __shared__ float sf[];
    float* Ks = sf;
    float* Vs = sf + 128*KSP;
    const int tid = threadIdx.x, lane = tid & 31, w = tid >> 5;
    const int g = lane >> 2, t = lane & 3;
    const int bh = blockIdx.y, b = bh >> 4, hh = bh & 15;
    const int bm = blockIdx.x * 128;
    const float* Qb = g_Q + (size_t)bh*SS*DHH;
    const float* Kb = g_K + (size_t)bh*KVL*DHH;
    const float* Vb = g_V + (size_t)bh*KVS*DHH;

    #pragma unroll
    for (int j = 0; j < 8; j++) {
        int idx = tid + j*256;
        int r = idx >> 4, c4 = idx & 15;
        float4 q = *(const float4*)(Qb + (size_t)(bm + r)*DHH + c4*4);
        float* p = Ks + r*KSP + c4*4;
        p[0]=cvtf(q.x); p[1]=cvtf(q.y); p[2]=cvtf(q.z); p[3]=cvtf(q.w);
    }
    __syncthreads();
    unsigned aQ[8][4];
    #pragma unroll
    for (int k = 0; k < 8; k++) {
        const float* p0 = Ks + (w*16 + g)*KSP + k*8;
        const float* p1 = p0 + 8*KSP;
        aQ[k][0] = ldsu(p0 + t);
        aQ[k][1] = ldsu(p1 + t);
        aQ[k][2] = ldsu(p0 + t + 4);
        aQ[k][3] = ldsu(p1 + t + 4);
    }
    __syncthreads();

    float accO[8][4];
    #pragma unroll
    for (int vn = 0; vn < 8; vn++)
        #pragma unroll
        for (int e = 0; e < 4; e++) accO[vn][e] = 0.f;
    float mrow0 = -1e30f, mrow1 = -1e30f, lrow0 = 0.f, lrow1 = 0.f;

    const int gi0 = bm + w*16 + g, gi1 = gi0 + 8;
    const float* am0 = attn_mask + ((size_t)b*SS + gi0)*SS;
    const float* am1 = attn_mask + ((size_t)b*SS + gi1)*SS;
    const bool iafh = (hh < NIAFH);

    for (int j0 = 0; j0 < KVL; j0 += 128) {
        #pragma unroll
        for (int j = 0; j < 8; j++) {
            int idx = tid + j*256;
            int r = idx >> 4, c4 = idx & 15;
            bool ok = (j0 + r) < KVL;
            float4 kv = ok ? *(const float4*)(Kb + (size_t)(j0 + r)*DHH + c4*4)
                           : make_float4(0.f,0.f,0.f,0.f);
            float* pk = Ks + r*KSP + c4*4;
            pk[0]=cvtf(kv.x); pk[1]=cvtf(kv.y); pk[2]=cvtf(kv.z); pk[3]=cvtf(kv.w);
            float4 vv = ok ? *(const float4*)(Vb + (size_t)(j0 + r)*DHH + c4*4)
                           : make_float4(0.f,0.f,0.f,0.f);
            float* pv = Vs + r*VSP + c4*4;
            pv[0]=cvtf(vv.x); pv[1]=cvtf(vv.y); pv[2]=cvtf(vv.z); pv[3]=cvtf(vv.w);
        }
        __syncthreads();

        float s[16][4];
        #pragma unroll
        for (int nt = 0; nt < 16; nt++)
            #pragma unroll
            for (int e = 0; e < 4; e++) s[nt][e] = 0.f;
        #pragma unroll
        for (int ks = 0; ks < 8; ks++) {
            #pragma unroll
            for (int nt = 0; nt < 16; nt++) {
                unsigned bb[2];
                const float* pn = Ks + (nt*8 + g)*KSP + ks*8;
                bb[0] = ldsu(pn + t);
                bb[1] = ldsu(pn + t + 4);
                mma8(s[nt], aQ[ks], bb);
            }
        }

        float tmax0 = -1e30f, tmax1 = -1e30f;
        #pragma unroll
        for (int nt = 0; nt < 16; nt++) {
            int colbase = j0 + nt*8;
            if (colbase >= KVL) {
                s[nt][0] = s[nt][1] = s[nt][2] = s[nt][3] = -1e30f;
            } else if (colbase < RG) {
                s[nt][0] *= 0.125f; s[nt][1] *= 0.125f;
                s[nt][2] *= 0.125f; s[nt][3] *= 0.125f;
            } else {
                int js = colbase + 2*t - RG;
                float2 a0 = *(const float2*)(am0 + js);
                float2 a1 = *(const float2*)(am1 + js);
                float mk00 = a0.x, mk01 = a0.y, mk10 = a1.x, mk11 = a1.y;
                if (iafh) {
                    if (js     >= gi0) mk00 += NEGV;
                    if (js + 1 >= gi0) mk01 += NEGV;
                    if (js     >= gi1) mk10 += NEGV;
                    if (js + 1 >= gi1) mk11 += NEGV;
                }
                s[nt][0] = s[nt][0]*0.125f + mk00;
                s[nt][1] = s[nt][1]*0.125f + mk01;
                s[nt][2] = s[nt][2]*0.125f + mk10;
                s[nt][3] = s[nt][3]*0.125f + mk11;
            }
            tmax0 = fmaxf(tmax0, fmaxf(s[nt][0], s[nt][1]));
            tmax1 = fmaxf(tmax1, fmaxf(s[nt][2], s[nt][3]));
        }
        tmax0 = fmaxf(tmax0, __shfl_xor_sync(0xffffffffu, tmax0, 1));
        tmax0 = fmaxf(tmax0, __shfl_xor_sync(0xffffffffu, tmax0, 2));
        tmax1 = fmaxf(tmax1, __shfl_xor_sync(0xffffffffu, tmax1, 1));
        tmax1 = fmaxf(tmax1, __shfl_xor_sync(0xffffffffu, tmax1, 2));

        float newm0 = fmaxf(mrow0, tmax0);
        float newm1 = fmaxf(mrow1, tmax1);
        float sc0 = __expf(mrow0 - newm0);
        float sc1 = __expf(mrow1 - newm1);
        float rs0 = 0.f, rs1 = 0.f;
        #pragma unroll
        for (int nt = 0; nt < 16; nt++) {
            float p0 = __expf(s[nt][0] - newm0);
            float p1 = __expf(s[nt][1] - newm0);
            float p2 = __expf(s[nt][2] - newm1);
            float p3 = __expf(s[nt][3] - newm1);
            s[nt][0] = p0; s[nt][1] = p1; s[nt][2] = p2; s[nt][3] = p3;
            rs0 += p0 + p1; rs1 += p2 + p3;
        }
        rs0 += __shfl_xor_sync(0xffffffffu, rs0, 1);
        rs0 += __shfl_xor_sync(0xffffffffu, rs0, 2);
        rs1 += __shfl_xor_sync(0xffffffffu, rs1, 1);
        rs1 += __shfl_xor_sync(0xffffffffu, rs1, 2);
        lrow0 = lrow0*sc0 + rs0;
        lrow1 = lrow1*sc1 + rs1;
        mrow0 = newm0; mrow1 = newm1;
        #pragma unroll
        for (int vn = 0; vn < 8; vn++) {
            accO[vn][0] *= sc0; accO[vn][1] *= sc0;
            accO[vn][2] *= sc1; accO[vn][3] *= sc1;
        }

        const int qb = lane & ~3;
        const int s0l = qb + (t >> 1), s1l = s0l + 2;
        const bool odd = (t & 1);
        #pragma unroll
        for (int ks = 0; ks < 16; ks++) {
            float x0 = __shfl_sync(0xffffffffu, s[ks][0], s0l);
            float x1 = __shfl_sync(0xffffffffu, s[ks][1], s0l);
            float y0 = __shfl_sync(0xffffffffu, s[ks][2], s0l);
            float y1 = __shfl_sync(0xffffffffu, s[ks][3], s0l);
            float x0b = __shfl_sync(0xffffffffu, s[ks][0], s1l);
            float x1b = __shfl_sync(0xffffffffu, s[ks][1], s1l);
            float y0b = __shfl_sync(0xffffffffu, s[ks][2], s1l);
            float y1b = __shfl_sync(0xffffffffu, s[ks][3], s1l);
            unsigned aP[4];
            aP[0] = cvt_tf32(odd ? x1  : x0);
            aP[1] = cvt_tf32(odd ? y1  : y0);
            aP[2] = cvt_tf32(odd ? x1b : x0b);
            aP[3] = cvt_tf32(odd ? y1b : y0b);
            #pragma unroll
            for (int vn = 0; vn < 8; vn++) {
                unsigned bb[2];
                bb[0] = ldsu(Vs + (ks*8 + t)*VSP + vn*8 + g);
                bb[1] = ldsu(Vs + (ks*8 + t + 4)*VSP + vn*8 + g);
                mma8(accO[vn], aP, bb);
            }
        }
        __syncthreads();
    }

    float inv0 = 1.f / lrow0, inv1 = 1.f / lrow1;
    int row0 = b*SS + gi0, row1 = b*SS + gi1;
    #pragma unroll
    for (int vn = 0; vn < 8; vn++) {
        int n = vn*8 + 2*t;
        *(__nv_bfloat162*)(g_down_b + (size_t)row0*DWK + ZD + hh*DHH + n) =
            __floats2bfloat162_rn(accO[vn][0]*inv0, accO[vn][1]*inv0);
        *(__nv_bfloat162*)(g_down_b + (size_t)row1*DWK + ZD + hh*DHH + n) =
            __floats2bfloat162_rn(accO[vn][2]*inv1, accO[vn][3]*inv1);
    }
}

// =======================================================================
// Kernel 5: mlp = silu(gate)*val into g_down_b (bf16x2)
// =======================================================================
__global__ void __launch_bounds__(256) mlp_kernel()
{
    size_t idx = (size_t)blockIdx.x*256 + threadIdx.x;   // over NTOK*MLPD/2
    int m = (int)(idx >> 11);
    int jj = (int)(idx & 2047);
    const __nv_bfloat162* gp = (const __nv_bfloat162*)(g_u_b + (size_t)m*UPN + 3*QKVD) + jj;
    const __nv_bfloat162* vp = (const __nv_bfloat162*)(g_u_b + (size_t)m*UPN + 3*QKVD + MLPD) + jj;
    float2 gv = __bfloat1622float2(*gp);
    float2 vv = __bfloat1622float2(*vp);
    float r0 = gv.x / (1.f + __expf(-gv.x)) * vv.x;
    float r1 = gv.y / (1.f + __expf(-gv.y)) * vv.y;
    *((__nv_bfloat162*)(g_down_b + (size_t)m*DWK + ZD + QKVD) + jj) =
        __floats2bfloat162_rn(r0, r1);
}

// =======================================================================
// launch
// =======================================================================
extern "C" void kernel_launch(void* const* d_in, const int* in_sizes, int n_in,
                              void* d_out, int out_size)
{
    const float* hs          = (const float*)d_in[0];
    const unsigned char* msk = (const unsigned char*)d_in[1];
    const float* noise       = (const float*)d_in[2];
    const float* next_noise  = (const float*)d_in[3];
    const float* attn_mask   = (const float*)d_in[4];
    const float* ln_w        = (const float*)d_in[5];
    const float* ln_b        = (const float*)d_in[6];
    const float* alpha       = (const float*)d_in[7];
    const float* iaf_wx      = (const float*)d_in[8];
    const float* iaf_wn      = (const float*)d_in[9];
    const float* iaf_w2      = (const float*)d_in[10];
    const float* up_w        = (const float*)d_in[11];
    const float* iaf_up_w    = (const float*)d_in[12];
    const float* down_w      = (const float*)d_in[13];
    const float* reg_k       = (const float*)d_in[14];
    const float* reg_v       = (const float*)d_in[15];
    float* out = (float*)d_out;

    __nv_bfloat16 *p_xz, *p_u, *p_down, *p_upw, *p_dnw, *p_xa, *p_wxs;
    float *p_hdnp;
    cudaGetSymbolAddress((void**)&p_xz, g_xz_b);
    cudaGetSymbolAddress((void**)&p_u, g_u_b);
    cudaGetSymbolAddress((void**)&p_down, g_down_b);
    cudaGetSymbolAddress((void**)&p_upw, g_upw_b);
    cudaGetSymbolAddress((void**)&p_dnw, g_dnw_b);
    cudaGetSymbolAddress((void**)&p_xa, g_xa);
    cudaGetSymbolAddress((void**)&p_wxs, g_wxs);
    cudaGetSymbolAddress((void**)&p_hdnp, g_hdnp);

    const int GEMM_SMEM = (2*128 + 2*256)*APITCH*2;   // 61440
    (void)cudaFuncSetAttribute(bf16_gemm_nt<0>, cudaFuncAttributeMaxDynamicSharedMemorySize, GEMM_SMEM);
    (void)cudaFuncSetAttribute(bf16_gemm_nt<1>, cudaFuncAttributeMaxDynamicSharedMemorySize, GEMM_SMEM);
    (void)cudaFuncSetAttribute(bf16_gemm_nt<2>, cudaFuncAttributeMaxDynamicSharedMemorySize, GEMM_SMEM);
    (void)cudaFuncSetAttribute(flash_kernel, cudaFuncAttributeMaxDynamicSharedMemorySize, FLASH_SMEM);

    RopeTab rt;
    for (int d = 0; d < 32; d++) {
        float pw = powf(10000.f, (float)(2*d) / 64.f);
        rt.inv[d] = 1.f / pw;
    }

    detect_mask_kernel<<<1, 32>>>(msk);

    // weight conversions (fp32 -> bf16)
    convert_bf16_kernel<<<(UPN*UPK/2 + 255)/256, 256>>>(up_w, p_upw, UPN*UPK/2);
    convert_bf16_kernel<<<(DD*DWK/2 + 255)/256, 256>>>(down_w, p_dnw, DD*DWK/2);
    convert_wxs_kernel<<<(HIAFP*DD + 255)/256, 256>>>(iaf_wx);

    // token path: LN -> split-precision iaf_wx GEMM (fp32 out) -> z/mu/sigma
    ln_kernel<<<NTOK, 128>>>(hs, ln_w, ln_b);
    bf16_gemm_nt<2><<<dim3(HIAFP/256, NTOK/128), 256, GEMM_SMEM>>>(
        p_xa, p_wxs, p_hdnp, NTOK, HIAFP, XAK, XAK, XAK, nullptr, nullptr);
    z_kernel<<<NTOK/8, 128>>>(msk, noise, iaf_wn, iaf_w2, out);

    bf16_gemm_nt<0><<<dim3(UPN/256, NTOK/128), 256, GEMM_SMEM>>>(
        p_xz, p_upw, p_u, NTOK, UPN, UPK, UPK, UPK, nullptr, nullptr);

    prep_qkv<<<NTOK/8, 256>>>(next_noise, iaf_up_w, rt);
    regfill_kernel<<<BB*NHH, 512>>>(reg_k, reg_v);

    flash_kernel<<<dim3(SS/128, BB*NHH), 256, FLASH_SMEM>>>(attn_mask);

    mlp_kernel<<<(NTOK*MLPD/2)/256, 256>>>();

    bf16_gemm_nt<1><<<dim3(DD/256, NTOK/128), 256, GEMM_SMEM>>>(
        p_down, p_dnw, out, NTOK, DD, DWK, DWK, DWK, hs, alpha);
}

// round 14
// speedup vs baseline: 3.8592x; 1.1062x over previous
#include <cuda_runtime.h>
#include <cuda_bf16.h>
#include <math.h>

// ---------------- problem constants ----------------
#define BB 2
#define SS 2048
#define DD 1024
#define NHH 16
#define DHH 64
#define NIAFH 4
#define QKVD 1024
#define MLPD 4096
#define ZD 32
#define HIAFD 128
#define HIAFP 256              // padded hdn width for GEMM (N%256==0)
#define XAK 3072               // split-GEMM K: [x_hi | x_hi | x_lo]
#define RG 8
#define KVL (SS + RG)          // 2056
#define KVS 2080               // padded V stride
#define UPN (QKVD + 2*QKVD + 2*MLPD)   // 11264
#define UPK (DD + ZD)          // 1056
#define DWK (ZD + QKVD + MLPD) // 5152
#define NTOK (BB*SS)           // 4096

#define ZSCALE 0.04419417382415922f    // sqrt(1/(32*16))
#define SPSHIFT 0.5413248546129181f    // log(e-1)
#define NEGV -1000000000.0f

// output layout: h_out | z | mu | sigma
#define OFF_Z  (NTOK*DD)
#define OFF_MU (OFF_Z + NTOK*ZD)
#define OFF_SG (OFF_MU + NTOK*ZD)

// ---------------- scratch ----------------
__device__ __nv_bfloat16 g_xz_b[(size_t)NTOK*UPK];     // [x | z] bf16
__device__ __nv_bfloat16 g_u_b[(size_t)NTOK*UPN];      // up-proj out bf16
__device__ __nv_bfloat16 g_down_b[(size_t)NTOK*DWK];   // [z|attn|mlp] bf16
__device__ __nv_bfloat16 g_upw_b[(size_t)UPN*UPK];     // bf16 up weights
__device__ __nv_bfloat16 g_dnw_b[(size_t)DD*DWK];      // bf16 down weights
__device__ __nv_bfloat16 g_xa[(size_t)NTOK*XAK];       // [x_hi | x_hi | x_lo]
__device__ __nv_bfloat16 g_wxs[(size_t)HIAFP*XAK];     // [w_hi | w_lo | w_hi] (pad rows 0)
__device__ float        g_hdnp[(size_t)NTOK*HIAFP];    // hdn pre-activation fp32
__device__ __nv_bfloat16 g_Qb[(size_t)BB*NHH*SS*DHH];  // roped Q bf16
__device__ __nv_bfloat16 g_Kb[(size_t)BB*NHH*KVL*DHH]; // registers + roped K bf16
__device__ __nv_bfloat16 g_Vb[(size_t)BB*NHH*KVS*DHH]; // registers + V bf16 (pad zero)
__device__ int   g_mask_mode;

struct RopeTab { float inv[32]; };

// ---------------- mma helpers ----------------
__device__ __forceinline__ void mma16bf(float* d, const unsigned* a, const unsigned* b) {
    asm volatile(
        "mma.sync.aligned.m16n8k16.row.col.f32.bf16.bf16.f32 "
        "{%0,%1,%2,%3}, {%4,%5,%6,%7}, {%8,%9}, {%0,%1,%2,%3};"
        : "+f"(d[0]), "+f"(d[1]), "+f"(d[2]), "+f"(d[3])
        : "r"(a[0]), "r"(a[1]), "r"(a[2]), "r"(a[3]), "r"(b[0]), "r"(b[1]));
}
__device__ __forceinline__ unsigned pack_bf(float a, float b) {
    __nv_bfloat162 h = __floats2bfloat162_rn(a, b);
    return *(unsigned*)&h;
}
__device__ __forceinline__ unsigned smem_u32(const void* p) {
    return (unsigned)__cvta_generic_to_shared(p);
}

// =======================================================================
// Kernel 0: classify the storage dtype of the bool `mask` input.
// =======================================================================
__global__ void detect_mask_kernel(const unsigned char* __restrict__ p)
{
    if (threadIdx.x != 0 || blockIdx.x != 0) return;
    const unsigned int* w = (const unsigned int*)p;
    bool allf = true, anyf = false, i32ok = true;
    for (int i = 0; i < 1024; i++) {
        unsigned int v = w[i];
        if (v == 0x3F800000u) anyf = true;
        else if (v != 0u) allf = false;
        if ((v & 0xFFFFFF00u) != 0u) i32ok = false;
    }
    g_mask_mode = (allf && anyf) ? 2 : (i32ok ? 1 : 0);
}

__device__ __forceinline__ float read_mask(const unsigned char* p, int m, int mode)
{
    if (mode == 1) return ((const int*)p)[m] != 0 ? 1.f : 0.f;
    if (mode == 2) return ((const float*)p)[m] != 0.f ? 1.f : 0.f;
    return p[m] != 0 ? 1.f : 0.f;
}

// =======================================================================
// Kernel 0b: fp32 -> bf16 conversion
// =======================================================================
__global__ void convert_bf16_kernel(const float* __restrict__ src,
                                    __nv_bfloat16* __restrict__ dst, int n2)
{
    int i = blockIdx.x*256 + threadIdx.x;
    if (i < n2) {
        float2 v = ((const float2*)src)[i];
        ((__nv_bfloat162*)dst)[i] = __floats2bfloat162_rn(v.x, v.y);
    }
}

// iaf_wx split: g_wxs[j][0..1023]=w_hi, [1024..2047]=w_lo, [2048..3071]=w_hi
__global__ void convert_wxs_kernel(const float* __restrict__ wx)
{
    int idx = blockIdx.x*256 + threadIdx.x;      // over HIAFP*DD
    if (idx >= HIAFP*DD) return;
    int j = idx >> 10, d = idx & 1023;
    __nv_bfloat16 hi, lo;
    if (j < HIAFD) {
        float w = wx[(size_t)j*DD + d];
        hi = __float2bfloat16(w);
        lo = __float2bfloat16(w - __bfloat162float(hi));
    } else {
        hi = __float2bfloat16(0.f);
        lo = __float2bfloat16(0.f);
    }
    __nv_bfloat16* row = g_wxs + (size_t)j*XAK;
    row[d] = hi;
    row[1024 + d] = lo;
    row[2048 + d] = hi;
}

// =======================================================================
// Kernel 1a: LayerNorm per token -> bf16 x (+ split hi/lo into g_xa)
// =======================================================================
__global__ void __launch_bounds__(128) ln_kernel(
    const float* __restrict__ hs,
    const float* __restrict__ ln_w, const float* __restrict__ ln_b)
{
    __shared__ float redS[4], redQ[4], stat[2];
    const int tid = threadIdx.x, lane = tid & 31, wid = tid >> 5;
    const int m = blockIdx.x;
    const float* hp = hs + (size_t)m*DD;

    float4 xv[2];
    float s = 0.f, q = 0.f;
    #pragma unroll
    for (int k = 0; k < 2; k++) {
        xv[k] = *(const float4*)(hp + tid*4 + k*512);
        s += xv[k].x + xv[k].y + xv[k].z + xv[k].w;
        q += xv[k].x*xv[k].x + xv[k].y*xv[k].y + xv[k].z*xv[k].z + xv[k].w*xv[k].w;
    }
    #pragma unroll
    for (int o = 16; o; o >>= 1) {
        s += __shfl_down_sync(0xffffffffu, s, o);
        q += __shfl_down_sync(0xffffffffu, q, o);
    }
    if (lane == 0) { redS[wid] = s; redQ[wid] = q; }
    __syncthreads();
    if (tid == 0) {
        float S1 = redS[0]+redS[1]+redS[2]+redS[3];
        float Q1 = redQ[0]+redQ[1]+redQ[2]+redQ[3];
        float mean = S1 / (float)DD;
        float var  = Q1 / (float)DD - mean*mean;
        stat[0] = mean;
        stat[1] = rsqrtf(var + 1e-5f);
    }
    __syncthreads();
    float mean = stat[0], rstd = stat[1];
    __nv_bfloat16* xzr = g_xz_b + (size_t)m*UPK;
    __nv_bfloat16* xar = g_xa + (size_t)m*XAK;
    #pragma unroll
    for (int k = 0; k < 2; k++) {
        int d = tid*4 + k*512;
        float4 wv = *(const float4*)(ln_w + d);
        float4 bv = *(const float4*)(ln_b + d);
        float xf[4];
        xf[0] = (xv[k].x - mean)*rstd*wv.x + bv.x;
        xf[1] = (xv[k].y - mean)*rstd*wv.y + bv.y;
        xf[2] = (xv[k].z - mean)*rstd*wv.z + bv.z;
        xf[3] = (xv[k].w - mean)*rstd*wv.w + bv.w;
        #pragma unroll
        for (int e = 0; e < 4; e++) {
            __nv_bfloat16 hi = __float2bfloat16(xf[e]);
            __nv_bfloat16 lo = __float2bfloat16(xf[e] - __bfloat162float(hi));
            xzr[d + e] = hi;
            xar[d + e] = hi;
            xar[1024 + d + e] = hi;
            xar[2048 + d + e] = lo;
        }
    }
}

// =======================================================================
// Kernel 1b: z/mu/sigma from fp32 hdn-pre + noise terms (8 tokens/block)
// =======================================================================
__global__ void __launch_bounds__(128) z_kernel(
    const unsigned char* __restrict__ mask, const float* __restrict__ noise,
    const float* __restrict__ iaf_wn, const float* __restrict__ iaf_w2,
    float* __restrict__ out)
{
    __shared__ float ns[8][ZD];
    __shared__ float hdn[8][HIAFD];
    __shared__ float zps[8][2*ZD];
    __shared__ float fmv[8];
    const int tid = threadIdx.x;
    const int m0 = blockIdx.x * 8;
    const int mmode = g_mask_mode;

    {
        int t = tid >> 5, i = tid & 31;
        float fm = read_mask(mask, m0 + t, mmode);
        ns[t][i] = noise[(size_t)(m0 + t)*ZD + i] * fm;
        ns[t + 4][i] = noise[(size_t)(m0 + t + 4)*ZD + i] *
                       read_mask(mask, m0 + t + 4, mmode);
        if (i == 0) {
            fmv[t] = fm;
            fmv[t + 4] = read_mask(mask, m0 + t + 4, mmode);
        }
    }
    __syncthreads();

    {
        int j = tid;
        float acc[8];
        #pragma unroll
        for (int t = 0; t < 8; t++)
            acc[t] = g_hdnp[(size_t)(m0 + t)*HIAFP + j];
        int dm = j % 31;                 // M1[j][i] = (i <= j%31)
        const float* wn = iaf_wn + (size_t)j*ZD;
        for (int i = 0; i <= dm; i++) {
            float w = wn[i];
            #pragma unroll
            for (int t = 0; t < 8; t++) acc[t] += ns[t][i]*w;
        }
        #pragma unroll
        for (int t = 0; t < 8; t++) {
            float v = acc[t];
            hdn[t][j] = v / (1.f + __expf(-v));
        }
    }
    __syncthreads();

    if (tid < 64) {
        int o = tid, lim = o & 31;       // M2[o][j] = (j%31 < o%32)
        float acc[8];
        #pragma unroll
        for (int t = 0; t < 8; t++) acc[t] = 0.f;
        const float* w2 = iaf_w2 + (size_t)o*HIAFD;
        for (int j = 0; j < HIAFD; j++) {
            if ((j % 31) < lim) {
                float w = w2[j];
                #pragma unroll
                for (int t = 0; t < 8; t++) acc[t] += hdn[t][j]*w;
            }
        }
        #pragma unroll
        for (int t = 0; t < 8; t++) zps[t][o] = fmv[t]*ZSCALE*acc[t];
    }
    __syncthreads();

    for (int idx = tid; idx < 8*ZD; idx += 128) {
        int t = idx >> 5, i = idx & 31;
        int m = m0 + t;
        float mu = zps[t][i];
        float ls = zps[t][ZD + i] + SPSHIFT;
        float sg = (ls > 20.f) ? ls : log1pf(expf(ls));
        float z  = mu + sg*ns[t][i];
        g_xz_b[(size_t)m*UPK + DD + i] = __float2bfloat16(z);
        g_down_b[(size_t)m*DWK + i]    = __float2bfloat16(z);
        out[OFF_Z  + (size_t)m*ZD + i] = z;
        out[OFF_MU + (size_t)m*ZD + i] = mu;
        out[OFF_SG + (size_t)m*ZD + i] = sg;
    }
}

// =======================================================================
// Kernel 2: BF16 GEMM 128x256x32, cp.async double-buffered, m16n8k16.
//   EPI=0: C bf16;  EPI=1: C fp32 = addsrc+alpha*acc;  EPI=2: C fp32 plain
// =======================================================================
#define APITCH 40

__device__ __forceinline__ void bgemm_prefetch(
    const __nv_bfloat16* __restrict__ A, const __nv_bfloat16* __restrict__ B,
    __nv_bfloat16* As, __nv_bfloat16* Bs, int bm, int bn, int lda, int ldb, int k0, int tid)
{
    #pragma unroll
    for (int j = 0; j < 2; j++) {
        int idx = tid + j*256, r = idx >> 2, c = idx & 3;
        unsigned d = smem_u32(As + r*APITCH + c*8);
        asm volatile("cp.async.ca.shared.global [%0], [%1], 16;"
                     :: "r"(d), "l"(A + (size_t)(bm + r)*lda + k0 + c*8));
    }
    #pragma unroll
    for (int j = 0; j < 4; j++) {
        int idx = tid + j*256, r = idx >> 2, c = idx & 3;
        unsigned d = smem_u32(Bs + r*APITCH + c*8);
        asm volatile("cp.async.ca.shared.global [%0], [%1], 16;"
                     :: "r"(d), "l"(B + (size_t)(bn + r)*ldb + k0 + c*8));
    }
}

template<int EPI>
__global__ void __launch_bounds__(256) bf16_gemm_nt(
    const __nv_bfloat16* __restrict__ A, const __nv_bfloat16* __restrict__ Bw, void* Cp,
    int M, int N, int K, int lda, int ldb,
    const float* __restrict__ addsrc, const float* __restrict__ alphap)
{
    extern __shared__ __nv_bfloat16 smb[];
    __nv_bfloat16* Asb[2] = { smb, smb + 128*APITCH };
    __nv_bfloat16* Bsb[2] = { smb + 2*128*APITCH, smb + 2*128*APITCH + 256*APITCH };
    const int tid = threadIdx.x;
    const int lane = tid & 31, wid = tid >> 5;
    const int g = lane >> 2, t = lane & 3;
    const int wm = (wid >> 2) * 64, wn = (wid & 3) * 64;
    const int bm = blockIdx.y * 128, bn = blockIdx.x * 256;

    float acc[4][8][4];
    #pragma unroll
    for (int mi = 0; mi < 4; mi++)
        #pragma unroll
        for (int ni = 0; ni < 8; ni++)
            #pragma unroll
            for (int e = 0; e < 4; e++) acc[mi][ni][e] = 0.f;

    const int KT = K / 32;
    bgemm_prefetch(A, Bw, Asb[0], Bsb[0], bm, bn, lda, ldb, 0, tid);
    asm volatile("cp.async.commit_group;");

    for (int kt = 0; kt < KT; kt++) {
        const int buf = kt & 1;
        if (kt + 1 < KT) {
            bgemm_prefetch(A, Bw, Asb[buf^1], Bsb[buf^1], bm, bn, lda, ldb, (kt+1)*32, tid);
            asm volatile("cp.async.commit_group;");
            asm volatile("cp.async.wait_group 1;");
        } else {
            asm volatile("cp.async.wait_group 0;");
        }
        __syncthreads();
        const __nv_bfloat16* As = Asb[buf];
        const __nv_bfloat16* Bs = Bsb[buf];
        #pragma unroll
        for (int ks = 0; ks < 32; ks += 16) {
            unsigned a[4][4], b[8][2];
            #pragma unroll
            for (int mi = 0; mi < 4; mi++) {
                const __nv_bfloat16* p0 = As + (wm + mi*16 + g)*APITCH + ks + 2*t;
                a[mi][0] = *(const unsigned*)(p0);
                a[mi][1] = *(const unsigned*)(p0 + 8*APITCH);
                a[mi][2] = *(const unsigned*)(p0 + 8);
                a[mi][3] = *(const unsigned*)(p0 + 8*APITCH + 8);
            }
            #pragma unroll
            for (int ni = 0; ni < 8; ni++) {
                const __nv_bfloat16* pn = Bs + (wn + ni*8 + g)*APITCH + ks + 2*t;
                b[ni][0] = *(const unsigned*)(pn);
                b[ni][1] = *(const unsigned*)(pn + 8);
            }
            #pragma unroll
            for (int mi = 0; mi < 4; mi++)
                #pragma unroll
                for (int ni = 0; ni < 8; ni++)
                    mma16bf(acc[mi][ni], a[mi], b[ni]);
        }
        __syncthreads();
    }

    float alpha = (EPI == 1) ? *alphap : 0.f;
    #pragma unroll
    for (int mi = 0; mi < 4; mi++) {
        int r0 = bm + wm + mi*16 + g;
        #pragma unroll
        for (int ni = 0; ni < 8; ni++) {
            int c0 = bn + wn + ni*8 + 2*t;
            #pragma unroll
            for (int h = 0; h < 2; h++) {
                int row = r0 + 8*h;
                size_t o = (size_t)row*N + c0;
                float v0 = acc[mi][ni][2*h], v1 = acc[mi][ni][2*h + 1];
                if (EPI == 1) {
                    float* C = (float*)Cp;
                    C[o]   = addsrc[o]   + alpha*v0;
                    C[o+1] = addsrc[o+1] + alpha*v1;
                } else if (EPI == 2) {
                    float* C = (float*)Cp;
                    C[o]   = v0;
                    C[o+1] = v1;
                } else {
                    __nv_bfloat16* C = (__nv_bfloat16*)Cp;
                    *(__nv_bfloat162*)(C + o) = __floats2bfloat162_rn(v0, v1);
                }
            }
        }
    }
}

// =======================================================================
// Kernel 3: QKV prep — 8 tokens/block, bf16 u reads, RoPE, bf16 QKV out
// =======================================================================
__global__ void __launch_bounds__(256) prep_qkv(
    const float* __restrict__ next_noise, const float* __restrict__ iaf_up_w, RopeTab tab)
{
    __shared__ float nn[8][ZD];
    __shared__ float kadds[8][256], vadds[8][256];
    const int tid = threadIdx.x;
    const int m0 = blockIdx.x * 8;

    {
        int t8 = tid >> 5, i = tid & 31;
        nn[t8][i] = next_noise[(size_t)(m0 + t8)*ZD + i];
    }
    __syncthreads();
    {
        const float* wk = iaf_up_w + (size_t)tid*ZD;
        const float* wv = iaf_up_w + (size_t)(QKVD + tid)*ZD;
        float ka[8], va[8];
        #pragma unroll
        for (int u = 0; u < 8; u++) { ka[u] = 0.f; va[u] = 0.f; }
        #pragma unroll 4
        for (int i = 0; i < ZD; i++) {
            float wki = wk[i], wvi = wv[i];
            #pragma unroll
            for (int u = 0; u < 8; u++) {
                ka[u] += nn[u][i]*wki;
                va[u] += nn[u][i]*wvi;
            }
        }
        #pragma unroll
        for (int u = 0; u < 8; u++) { kadds[u][tid] = ka[u]; vadds[u][tid] = va[u]; }
    }
    __syncthreads();

    const int dd = tid & 31;
    for (int u = 0; u < 8; u++) {
        int m = m0 + u;
        int b = m >> 11, spos = m & 2047;
        const __nv_bfloat16* um = g_u_b + (size_t)m*UPN;
        float ang = (float)spos * tab.inv[dd];
        float c, sn; sincosf(ang, &sn, &c);
        #pragma unroll
        for (int pp = 0; pp < 2; pp++) {
            int p = tid + pp*256;            // 0..511
            int hh = p >> 5;
            int i1 = hh*DHH + dd, i2 = i1 + 32;
            float q1 = __bfloat162float(um[i1]);
            float q2 = __bfloat162float(um[i2]);
            size_t qo = (((size_t)(b*NHH + hh))*SS + spos)*DHH;
            g_Qb[qo + dd]      = __float2bfloat16(q1*c - q2*sn);
            g_Qb[qo + 32 + dd] = __float2bfloat16(q2*c + q1*sn);
            float k1 = __bfloat162float(um[QKVD + i1]) + (i1 < 256 ? kadds[u][i1] : 0.f);
            float k2 = __bfloat162float(um[QKVD + i2]) + (i2 < 256 ? kadds[u][i2] : 0.f);
            size_t ko = (((size_t)(b*NHH + hh))*KVL + RG + spos)*DHH;
            g_Kb[ko + dd]      = __float2bfloat16(k1*c - k2*sn);
            g_Kb[ko + 32 + dd] = __float2bfloat16(k2*c + k1*sn);
        }
        #pragma unroll
        for (int pp = 0; pp < 4; pp++) {
            int p = tid + pp*256;            // 0..1023
            int hh = p >> 6;
            float vv = __bfloat162float(um[2*QKVD + p]) + (p < 256 ? vadds[u][p] : 0.f);
            g_Vb[(((size_t)(b*NHH + hh))*KVS + RG + spos)*DHH + (p & 63)] = __float2bfloat16(vv);
        }
    }
}

// register tokens K/V fill + V pad-row zeroing
__global__ void regfill_kernel(const float* __restrict__ reg_k, const float* __restrict__ reg_v)
{
    int bh = blockIdx.x, hh = bh & 15;
    int j = threadIdx.x >> 6, d = threadIdx.x & 63;
    g_Kb[((size_t)bh*KVL + j)*DHH + d] = __float2bfloat16(reg_k[((size_t)j*NHH + hh)*DHH + d]);
    g_Vb[((size_t)bh*KVS + j)*DHH + d] = __float2bfloat16(reg_v[((size_t)j*NHH + hh)*DHH + d]);
    for (int idx = threadIdx.x; idx < (KVS - KVL)*DHH; idx += blockDim.x)
        g_Vb[((size_t)bh*KVS + KVL)*DHH + idx] = __float2bfloat16(0.f);
}

// =======================================================================
// Kernel 4: FLASH attention, all-bf16 mma (m16n8k16), no P shuffles
// =======================================================================
#define KSPb 72     // Ks pitch (bf16), rows = q/k tokens
#define VSPb 134    // Vs pitch (bf16), rows = head dim (n-major, transposed)
#define FLASH_SMEM (128*KSPb*2 + 64*VSPb*2)   // 35584 B

__global__ void __launch_bounds__(256) flash_kernel(const float* __restrict__ attn_mask)
{
    extern __shared__ __nv_bfloat16 sfb[];
    __nv_bfloat16* Ks = sfb;
    __nv_bfloat16* Vs = sfb + 128*KSPb;
    const int tid = threadIdx.x, lane = tid & 31, w = tid >> 5;
    const int g = lane >> 2, t = lane & 3;
    const int bh = blockIdx.y, b = bh >> 4, hh = bh & 15;
    const int bm = blockIdx.x * 128;
    const __nv_bfloat16* Qb = g_Qb + (size_t)bh*SS*DHH;
    const __nv_bfloat16* Kb = g_Kb + (size_t)bh*KVL*DHH;
    const __nv_bfloat16* Vb = g_Vb + (size_t)bh*KVS*DHH;

    // stage Q tile (bf16 copy), gather bf16 A-frags
    #pragma unroll
    for (int j = 0; j < 4; j++) {
        int idx = tid + j*256, r = idx >> 3, c8 = (idx & 7)*8;
        *(uint4*)(Ks + r*KSPb + c8) = *(const uint4*)(Qb + (size_t)(bm + r)*DHH + c8);
    }
    __syncthreads();
    unsigned aQ[4][4];
    #pragma unroll
    for (int ks = 0; ks < 4; ks++) {
        const __nv_bfloat16* p0 = Ks + (w*16 + g)*KSPb + ks*16 + 2*t;
        aQ[ks][0] = *(const unsigned*)(p0);
        aQ[ks][1] = *(const unsigned*)(p0 + 8*KSPb);
        aQ[ks][2] = *(const unsigned*)(p0 + 8);
        aQ[ks][3] = *(const unsigned*)(p0 + 8*KSPb + 8);
    }
    __syncthreads();

    float accO[8][4];
    #pragma unroll
    for (int vn = 0; vn < 8; vn++)
        #pragma unroll
        for (int e = 0; e < 4; e++) accO[vn][e] = 0.f;
    float mrow0 = -1e30f, mrow1 = -1e30f, lrow0 = 0.f, lrow1 = 0.f;

    const int gi0 = bm + w*16 + g, gi1 = gi0 + 8;
    const float* am0 = attn_mask + ((size_t)b*SS + gi0)*SS;
    const float* am1 = attn_mask + ((size_t)b*SS + gi1)*SS;
    const bool iafh = (hh < NIAFH);

    for (int j0 = 0; j0 < KVL; j0 += 128) {
        // K tile: bf16 copy (zero rows >= KVL)
        #pragma unroll
        for (int j = 0; j < 4; j++) {
            int idx = tid + j*256, r = idx >> 3, c8 = (idx & 7)*8;
            uint4 v = (j0 + r < KVL)
                    ? *(const uint4*)(Kb + (size_t)(j0 + r)*DHH + c8)
                    : make_uint4(0u, 0u, 0u, 0u);
            *(uint4*)(Ks + r*KSPb + c8) = v;
        }
        // V tile: transposed store -> Vs[n][k]
        #pragma unroll
        for (int j = 0; j < 4; j++) {
            int idx = tid + j*256, r = idx >> 3, c8 = (idx & 7)*8;
            uint4 v = (j0 + r < KVL)
                    ? *(const uint4*)(Vb + (size_t)(j0 + r)*DHH + c8)
                    : make_uint4(0u, 0u, 0u, 0u);
            __nv_bfloat16 h[8];
            *(uint4*)h = v;
            #pragma unroll
            for (int i = 0; i < 8; i++)
                Vs[(c8 + i)*VSPb + r] = h[i];
        }
        __syncthreads();

        // S = Q K^T  (bf16 mma, 4 k-steps of 16)
        float s[16][4];
        #pragma unroll
        for (int nt = 0; nt < 16; nt++)
            #pragma unroll
            for (int e = 0; e < 4; e++) s[nt][e] = 0.f;
        #pragma unroll
        for (int ks = 0; ks < 4; ks++) {
            #pragma unroll
            for (int nt = 0; nt < 16; nt++) {
                unsigned bb[2];
                const __nv_bfloat16* pn = Ks + (nt*8 + g)*KSPb + ks*16 + 2*t;
                bb[0] = *(const unsigned*)(pn);
                bb[1] = *(const unsigned*)(pn + 8);
                mma16bf(s[nt], aQ[ks], bb);
            }
        }

        // scale + mask + tile max
        float tmax0 = -1e30f, tmax1 = -1e30f;
        #pragma unroll
        for (int nt = 0; nt < 16; nt++) {
            int colbase = j0 + nt*8;
            if (colbase >= KVL) {
                s[nt][0] = s[nt][1] = s[nt][2] = s[nt][3] = -1e30f;
            } else if (colbase < RG) {
                s[nt][0] *= 0.125f; s[nt][1] *= 0.125f;
                s[nt][2] *= 0.125f; s[nt][3] *= 0.125f;
            } else {
                int js = colbase + 2*t - RG;
                float2 a0 = *(const float2*)(am0 + js);
                float2 a1 = *(const float2*)(am1 + js);
                float mk00 = a0.x, mk01 = a0.y, mk10 = a1.x, mk11 = a1.y;
                if (iafh) {
                    if (js     >= gi0) mk00 += NEGV;
                    if (js + 1 >= gi0) mk01 += NEGV;
                    if (js     >= gi1) mk10 += NEGV;
                    if (js + 1 >= gi1) mk11 += NEGV;
                }
                s[nt][0] = s[nt][0]*0.125f + mk00;
                s[nt][1] = s[nt][1]*0.125f + mk01;
                s[nt][2] = s[nt][2]*0.125f + mk10;
                s[nt][3] = s[nt][3]*0.125f + mk11;
            }
            tmax0 = fmaxf(tmax0, fmaxf(s[nt][0], s[nt][1]));
            tmax1 = fmaxf(tmax1, fmaxf(s[nt][2], s[nt][3]));
        }
        tmax0 = fmaxf(tmax0, __shfl_xor_sync(0xffffffffu, tmax0, 1));
        tmax0 = fmaxf(tmax0, __shfl_xor_sync(0xffffffffu, tmax0, 2));
        tmax1 = fmaxf(tmax1, __shfl_xor_sync(0xffffffffu, tmax1, 1));
        tmax1 = fmaxf(tmax1, __shfl_xor_sync(0xffffffffu, tmax1, 2));

        float newm0 = fmaxf(mrow0, tmax0);
        float newm1 = fmaxf(mrow1, tmax1);
        float sc0 = __expf(mrow0 - newm0);
        float sc1 = __expf(mrow1 - newm1);
        float rs0 = 0.f, rs1 = 0.f;
        #pragma unroll
        for (int nt = 0; nt < 16; nt++) {
            float p0 = __expf(s[nt][0] - newm0);
            float p1 = __expf(s[nt][1] - newm0);
            float p2 = __expf(s[nt][2] - newm1);
            float p3 = __expf(s[nt][3] - newm1);
            s[nt][0] = p0; s[nt][1] = p1; s[nt][2] = p2; s[nt][3] = p3;
            rs0 += p0 + p1; rs1 += p2 + p3;
        }
        rs0 += __shfl_xor_sync(0xffffffffu, rs0, 1);
        rs0 += __shfl_xor_sync(0xffffffffu, rs0, 2);
        rs1 += __shfl_xor_sync(0xffffffffu, rs1, 1);
        rs1 += __shfl_xor_sync(0xffffffffu, rs1, 2);
        lrow0 = lrow0*sc0 + rs0;
        lrow1 = lrow1*sc1 + rs1;
        mrow0 = newm0; mrow1 = newm1;
        #pragma unroll
        for (int vn = 0; vn < 8; vn++) {
            accO[vn][0] *= sc0; accO[vn][1] *= sc0;
            accO[vn][2] *= sc1; accO[vn][3] *= sc1;
        }

        // PV: P C-frag -> bf16 A-frag directly (no shuffles), V from Vs[n][k]
        #pragma unroll
        for (int ks = 0; ks < 8; ks++) {
            unsigned aP[4];
            aP[0] = pack_bf(s[2*ks][0],     s[2*ks][1]);
            aP[1] = pack_bf(s[2*ks][2],     s[2*ks][3]);
            aP[2] = pack_bf(s[2*ks + 1][0], s[2*ks + 1][1]);
            aP[3] = pack_bf(s[2*ks + 1][2], s[2*ks + 1][3]);
            #pragma unroll
            for (int vn = 0; vn < 8; vn++) {
                unsigned bb[2];
                const __nv_bfloat16* pv = Vs + (vn*8 + g)*VSPb + ks*16 + 2*t;
                bb[0] = *(const unsigned*)(pv);
                bb[1] = *(const unsigned*)(pv + 8);
                mma16bf(accO[vn], aP, bb);
            }
        }
        __syncthreads();
    }

    float inv0 = 1.f / lrow0, inv1 = 1.f / lrow1;
    int row0 = b*SS + gi0, row1 = b*SS + gi1;
    #pragma unroll
    for (int vn = 0; vn < 8; vn++) {
        int n = vn*8 + 2*t;
        *(__nv_bfloat162*)(g_down_b + (size_t)row0*DWK + ZD + hh*DHH + n) =
            __floats2bfloat162_rn(accO[vn][0]*inv0, accO[vn][1]*inv0);
        *(__nv_bfloat162*)(g_down_b + (size_t)row1*DWK + ZD + hh*DHH + n) =
            __floats2bfloat162_rn(accO[vn][2]*inv1, accO[vn][3]*inv1);
    }
}

// =======================================================================
// Kernel 5: mlp = silu(gate)*val into g_down_b (bf16x2)
// =======================================================================
__global__ void __launch_bounds__(256) mlp_kernel()
{
    size_t idx = (size_t)blockIdx.x*256 + threadIdx.x;   // over NTOK*MLPD/2
    int m = (int)(idx >> 11);
    int jj = (int)(idx & 2047);
    const __nv_bfloat162* gp = (const __nv_bfloat162*)(g_u_b + (size_t)m*UPN + 3*QKVD) + jj;
    const __nv_bfloat162* vp = (const __nv_bfloat162*)(g_u_b + (size_t)m*UPN + 3*QKVD + MLPD) + jj;
    float2 gv = __bfloat1622float2(*gp);
    float2 vv = __bfloat1622float2(*vp);
    float r0 = gv.x / (1.f + __expf(-gv.x)) * vv.x;
    float r1 = gv.y / (1.f + __expf(-gv.y)) * vv.y;
    *((__nv_bfloat162*)(g_down_b + (size_t)m*DWK + ZD + QKVD) + jj) =
        __floats2bfloat162_rn(r0, r1);
}

// =======================================================================
// launch
// =======================================================================
extern "C" void kernel_launch(void* const* d_in, const int* in_sizes, int n_in,
                              void* d_out, int out_size)
{
    const float* hs          = (const float*)d_in[0];
    const unsigned char* msk = (const unsigned char*)d_in[1];
    const float* noise       = (const float*)d_in[2];
    const float* next_noise  = (const float*)d_in[3];
    const float* attn_mask   = (const float*)d_in[4];
    const float* ln_w        = (const float*)d_in[5];
    const float* ln_b        = (const float*)d_in[6];
    const float* alpha       = (const float*)d_in[7];
    const float* iaf_wx      = (const float*)d_in[8];
    const float* iaf_wn      = (const float*)d_in[9];
    const float* iaf_w2      = (const float*)d_in[10];
    const float* up_w        = (const float*)d_in[11];
    const float* iaf_up_w    = (const float*)d_in[12];
    const float* down_w      = (const float*)d_in[13];
    const float* reg_k       = (const float*)d_in[14];
    const float* reg_v       = (const float*)d_in[15];
    float* out = (float*)d_out;

    __nv_bfloat16 *p_xz, *p_u, *p_down, *p_upw, *p_dnw, *p_xa, *p_wxs;
    float *p_hdnp;
    cudaGetSymbolAddress((void**)&p_xz, g_xz_b);
    cudaGetSymbolAddress((void**)&p_u, g_u_b);
    cudaGetSymbolAddress((void**)&p_down, g_down_b);
    cudaGetSymbolAddress((void**)&p_upw, g_upw_b);
    cudaGetSymbolAddress((void**)&p_dnw, g_dnw_b);
    cudaGetSymbolAddress((void**)&p_xa, g_xa);
    cudaGetSymbolAddress((void**)&p_wxs, g_wxs);
    cudaGetSymbolAddress((void**)&p_hdnp, g_hdnp);

    const int GEMM_SMEM = (2*128 + 2*256)*APITCH*2;   // 61440
    (void)cudaFuncSetAttribute(bf16_gemm_nt<0>, cudaFuncAttributeMaxDynamicSharedMemorySize, GEMM_SMEM);
    (void)cudaFuncSetAttribute(bf16_gemm_nt<1>, cudaFuncAttributeMaxDynamicSharedMemorySize, GEMM_SMEM);
    (void)cudaFuncSetAttribute(bf16_gemm_nt<2>, cudaFuncAttributeMaxDynamicSharedMemorySize, GEMM_SMEM);
    (void)cudaFuncSetAttribute(flash_kernel, cudaFuncAttributeMaxDynamicSharedMemorySize, FLASH_SMEM);

    RopeTab rt;
    for (int d = 0; d < 32; d++) {
        float pw = powf(10000.f, (float)(2*d) / 64.f);
        rt.inv[d] = 1.f / pw;
    }

    detect_mask_kernel<<<1, 32>>>(msk);

    // weight conversions (fp32 -> bf16)
    convert_bf16_kernel<<<(UPN*UPK/2 + 255)/256, 256>>>(up_w, p_upw, UPN*UPK/2);
    convert_bf16_kernel<<<(DD*DWK/2 + 255)/256, 256>>>(down_w, p_dnw, DD*DWK/2);
    convert_wxs_kernel<<<(HIAFP*DD + 255)/256, 256>>>(iaf_wx);

    // token path: LN -> split-precision iaf_wx GEMM (fp32 out) -> z/mu/sigma
    ln_kernel<<<NTOK, 128>>>(hs, ln_w, ln_b);
    bf16_gemm_nt<2><<<dim3(HIAFP/256, NTOK/128), 256, GEMM_SMEM>>>(
        p_xa, p_wxs, p_hdnp, NTOK, HIAFP, XAK, XAK, XAK, nullptr, nullptr);
    z_kernel<<<NTOK/8, 128>>>(msk, noise, iaf_wn, iaf_w2, out);

    bf16_gemm_nt<0><<<dim3(UPN/256, NTOK/128), 256, GEMM_SMEM>>>(
        p_xz, p_upw, p_u, NTOK, UPN, UPK, UPK, UPK, nullptr, nullptr);

    prep_qkv<<<NTOK/8, 256>>>(next_noise, iaf_up_w, rt);
    regfill_kernel<<<BB*NHH, 512>>>(reg_k, reg_v);

    flash_kernel<<<dim3(SS/128, BB*NHH), 256, FLASH_SMEM>>>(attn_mask);

    mlp_kernel<<<(NTOK*MLPD/2)/256, 256>>>();

    bf16_gemm_nt<1><<<dim3(DD/256, NTOK/128), 256, GEMM_SMEM>>>(
        p_down, p_dnw, out, NTOK, DD, DWK, DWK, DWK, hs, alpha);
}